// round 10
// baseline (speedup 1.0000x reference)
#include <cuda_runtime.h>
#include <cuda_bf16.h>
#include <cstdint>

#define N_NODES 100000
#define N_EDGES 1600000
#define HIDDEN 128
#define NUM_CLASSES 10
#define NUM_LAYERS 4
#define NUM_GRAPHS 200
#define BN_EPS 1e-5f

// ---------------- scratch (static device arrays: no allocations) ----------------
__device__ float d_h[(size_t)N_NODES * HIDDEN];             // exact fp32 state
__device__ __nv_bfloat16 d_h_bf0[(size_t)N_NODES * HIDDEN]; // bf16 ping
__device__ __nv_bfloat16 d_h_bf1[(size_t)N_NODES * HIDDEN]; // bf16 pong
__device__ float d_m[(size_t)N_NODES * HIDDEN];             // fc1 output
__device__ __nv_bfloat16 d_Wcomb_bf[NUM_LAYERS * 3 * HIDDEN * HIDDEN];
__device__ __nv_bfloat16 d_whh_bf[3 * HIDDEN * HIDDEN];
__device__ int d_src[N_EDGES];
__device__ int d_dst[N_EDGES];
__device__ int d_deg[N_NODES];
__device__ int d_rowptr[N_NODES + 1];
__device__ int d_cursor[N_NODES];
__device__ int d_colidx[N_EDGES];
__device__ int d_blocksum[128];
__device__ int d_blockoff[128];
__device__ float d_sum[HIDDEN], d_sumsq[HIDDEN], d_mean[HIDDEN], d_rstd[HIDDEN];
__device__ float d_pool[NUM_GRAPHS * HIDDEN];
__device__ int d_cnt[NUM_GRAPHS];

// ---------------- helpers ----------------
__device__ __forceinline__ float sigm_f(float x) {
    return __fdividef(1.f, 1.f + __expf(-x));
}
__device__ __forceinline__ float tanh_f(float x) {
    return 1.f - __fdividef(2.f, __expf(2.f * x) + 1.f);
}
__device__ __forceinline__ uint32_t smem_u32(const void* p) {
    uint32_t a;
    asm("{ .reg .u64 t; cvta.to.shared.u64 t, %1; cvt.u32.u64 %0, t; }" : "=r"(a) : "l"(p));
    return a;
}
__device__ __forceinline__ uint32_t f2tf32(float f) {
    uint32_t r;
    asm("cvt.rna.tf32.f32 %0, %1;" : "=r"(r) : "f"(f));
    return r;
}
__device__ __forceinline__ uint32_t bf2(float lo, float hi) {
    __nv_bfloat162 p = __floats2bfloat162_rn(lo, hi);
    return *(uint32_t*)&p;
}
__device__ __forceinline__ void mma_tf32(float* c, const uint32_t* a, const uint32_t* b) {
    asm volatile(
        "mma.sync.aligned.m16n8k8.row.col.f32.tf32.tf32.f32 "
        "{%0,%1,%2,%3}, {%4,%5,%6,%7}, {%8,%9}, {%0,%1,%2,%3};"
        : "+f"(c[0]), "+f"(c[1]), "+f"(c[2]), "+f"(c[3])
        : "r"(a[0]), "r"(a[1]), "r"(a[2]), "r"(a[3]), "r"(b[0]), "r"(b[1]));
}
__device__ __forceinline__ void mma_bf16(float* c, const uint32_t* a, const uint32_t* b) {
    asm volatile(
        "mma.sync.aligned.m16n8k16.row.col.f32.bf16.bf16.f32 "
        "{%0,%1,%2,%3}, {%4,%5,%6,%7}, {%8,%9}, {%0,%1,%2,%3};"
        : "+f"(c[0]), "+f"(c[1]), "+f"(c[2]), "+f"(c[3])
        : "r"(a[0]), "r"(a[1]), "r"(a[2]), "r"(a[3]), "r"(b[0]), "r"(b[1]));
}
__device__ __forceinline__ void cpasync16(uint32_t daddr, const void* src, int srcbytes) {
    asm volatile("cp.async.cg.shared.global [%0], [%1], 16, %2;"
                 :: "r"(daddr), "l"(src), "r"(srcbytes));
}
__device__ __forceinline__ void cpasync_commit() {
    asm volatile("cp.async.commit_group;" ::: "memory");
}

#define ASTRIDE 36
// gru smem (uint32 words, each = one bf16x2): A [64 rows][132], B 3 x [128][36]
#define S2A 132
#define S2B 36
#define AS_W (64 * S2A)
#define BS_W (128 * S2B)
#define GRU_SMEM_BYTES ((AS_W + 3 * BS_W) * 4)  // 89088 B -> 2 CTAs/SM

// ============ fused GRU layer (bf16 MMA + in-kernel CSR gather) ============
// 64 rows/block, 512 thr, 3-deep cp.async weight ring, h_bf ping-pong.
// Gate g: out = hsum @ Wcomb_g^T + h @ Whh_g^T (K=256 = 4 sub-chunks of 64 halves).
// 12 chunks: pass R(g=0) 0-3, N(g=2) 4-7, Z(g=1) 8-11.
__device__ __forceinline__ void gru_issueB(uint32_t bufaddr, const __nv_bfloat16* __restrict__ wcomb,
                                           int chunk, int tid) {
    int pass = chunk >> 2;
    int g = (pass == 0) ? 0 : (pass == 1) ? 2 : 1;
    int sub = chunk & 3;
    const __nv_bfloat16* base = ((sub < 2) ? wcomb : d_whh_bf) +
                                (size_t)g * 128 * HIDDEN + (sub & 1) * 64;
#pragma unroll
    for (int q = tid; q < 1024; q += 512) {
        int n = q >> 3, o = q & 7;
        cpasync16(bufaddr + (n * S2B + o * 4) * 4, base + (size_t)n * HIDDEN + o * 8, 16);
    }
    cpasync_commit();
}

__global__ void __launch_bounds__(512, 1) k_gru_fused(
    int layer, int pp, const float* __restrict__ bih, const float* __restrict__ bhh)
{
    extern __shared__ uint32_t dsm[];
    const __nv_bfloat16* wcomb = d_Wcomb_bf + (size_t)layer * 3 * HIDDEN * HIDDEN;
    const __nv_bfloat16* hcur = pp ? d_h_bf1 : d_h_bf0;
    __nv_bfloat16* hnxt = pp ? d_h_bf0 : d_h_bf1;
    const uint32_t sb = smem_u32(dsm);
    const uint32_t sbB = sb + AS_W * 4;

    const int tid = threadIdx.x, lane = tid & 31, w = tid >> 5;
    const int wm = w & 3, wn = w >> 2;  // 4 m-strips x 4 n-strips
    const int gid = lane >> 2, tg = lane & 3;
    const int row0 = blockIdx.x * 64;
    const int lr1 = wm * 16 + gid, lr2 = lr1 + 8;

    // ---- prologue: async-stage A h-half + weight chunks 0,1 ----
#pragma unroll
    for (int q = tid; q < 1024; q += 512) {
        int r = q >> 4, o = q & 15;  // 16 x 16B per row (h half: words 64..127)
        int gr = row0 + r;
        int ok = (gr < N_NODES);
        if (!ok) gr = 0;
        cpasync16(sb + (r * S2A + 64 + o * 4) * 4,
                  hcur + (size_t)gr * HIDDEN + o * 8, ok ? 16 : 0);
    }
    gru_issueB(sbB, wcomb, 0, tid);                 // A-h + B0 in one group
    gru_issueB(sbB + BS_W * 4, wcomb, 1, tid);      // B1

    // ---- in-kernel CSR gather: warp w sums neighbors for rows w*4..w*4+3 ----
    {
        const uint2* hb = (const uint2*)hcur;  // 32 uint2 per node row
#pragma unroll
        for (int rr4 = 0; rr4 < 4; rr4++) {
            int r = w * 4 + rr4;
            int gr = row0 + r;
            if (gr < N_NODES) {
                int beg = d_rowptr[gr], end = d_rowptr[gr + 1];
                float4 acc = make_float4(0.f, 0.f, 0.f, 0.f);
                for (int e = beg; e < end; e++) {
                    int src = d_colidx[e];
                    uint2 v = hb[(size_t)src * 32 + lane];
                    float2 f0 = __bfloat1622float2(*(__nv_bfloat162*)&v.x);
                    float2 f1 = __bfloat1622float2(*(__nv_bfloat162*)&v.y);
                    acc.x += f0.x; acc.y += f0.y; acc.z += f1.x; acc.w += f1.y;
                }
                // agg occupies words 0..63 of A row: lane covers words lane*2, lane*2+1
                *(uint2*)&dsm[r * S2A + lane * 2] =
                    make_uint2(bf2(acc.x, acc.y), bf2(acc.z, acc.w));
            }
        }
    }

    float rr[4][4], nn[4][4], ci[4][4], ch[4][4];
#pragma unroll
    for (int j = 0; j < 4; j++)
#pragma unroll
        for (int q = 0; q < 4; q++) { ci[j][q] = 0.f; ch[j][q] = 0.f; }

    for (int it = 0; it < 12; it++) {
        if (it < 11) asm volatile("cp.async.wait_group 1;" ::: "memory");
        else asm volatile("cp.async.wait_group 0;" ::: "memory");
        __syncthreads();

        if (it + 2 < 12) gru_issueB(sbB + ((it + 2) % 3) * BS_W * 4, wcomb, it + 2, tid);

        const uint32_t* BS = dsm + AS_W + (it % 3) * BS_W;
        const int pass = it >> 2, sub = it & 3;
        float(*acc)[4] = (pass == 1 && sub >= 2) ? ch : ci;
        const int kbase = sub * 32;  // half2 units
#pragma unroll
        for (int ks = 0; ks < 4; ks++) {
            int kb = kbase + ks * 8;
            uint32_t af[4];
            af[0] = dsm[lr1 * S2A + kb + tg];
            af[1] = dsm[lr2 * S2A + kb + tg];
            af[2] = dsm[lr1 * S2A + kb + tg + 4];
            af[3] = dsm[lr2 * S2A + kb + tg + 4];
#pragma unroll
            for (int nt = 0; nt < 4; nt++) {
                uint32_t bf[2];
                int nb = wn * 32 + nt * 8 + gid;
                bf[0] = BS[nb * S2B + ks * 8 + tg];
                bf[1] = BS[nb * S2B + ks * 8 + tg + 4];
                mma_bf16(acc[nt], af, bf);
            }
        }

        if (sub == 3) {
            if (pass == 0) {  // R
#pragma unroll
                for (int nt = 0; nt < 4; nt++) {
                    int coli = wn * 32 + nt * 8 + tg * 2;
                    float b0 = bih[coli] + bhh[coli];
                    float b1 = bih[coli + 1] + bhh[coli + 1];
                    rr[nt][0] = sigm_f(ci[nt][0] + b0);
                    rr[nt][1] = sigm_f(ci[nt][1] + b1);
                    rr[nt][2] = sigm_f(ci[nt][2] + b0);
                    rr[nt][3] = sigm_f(ci[nt][3] + b1);
#pragma unroll
                    for (int q = 0; q < 4; q++) ci[nt][q] = 0.f;
                }
            } else if (pass == 1) {  // N
#pragma unroll
                for (int nt = 0; nt < 4; nt++) {
                    int coli = wn * 32 + nt * 8 + tg * 2;
                    float bi0 = bih[256 + coli], bi1 = bih[256 + coli + 1];
                    float bh0 = bhh[256 + coli], bh1 = bhh[256 + coli + 1];
                    nn[nt][0] = tanh_f(ci[nt][0] + bi0 + rr[nt][0] * (ch[nt][0] + bh0));
                    nn[nt][1] = tanh_f(ci[nt][1] + bi1 + rr[nt][1] * (ch[nt][1] + bh1));
                    nn[nt][2] = tanh_f(ci[nt][2] + bi0 + rr[nt][2] * (ch[nt][2] + bh0));
                    nn[nt][3] = tanh_f(ci[nt][3] + bi1 + rr[nt][3] * (ch[nt][3] + bh1));
#pragma unroll
                    for (int q = 0; q < 4; q++) ci[nt][q] = 0.f;
                }
            } else {  // Z + in-place h update (fp32 + bf16 ping-pong mirror)
                int gr1 = row0 + lr1, gr2 = row0 + lr2;
#pragma unroll
                for (int nt = 0; nt < 4; nt++) {
                    int coli = wn * 32 + nt * 8 + tg * 2;
                    float b0 = bih[128 + coli] + bhh[128 + coli];
                    float b1 = bih[128 + coli + 1] + bhh[128 + coli + 1];
                    if (gr1 < N_NODES) {
                        float* hp = d_h + (size_t)gr1 * HIDDEN + coli;
                        float2 h = *(float2*)hp;
                        float z0 = sigm_f(ci[nt][0] + b0), z1 = sigm_f(ci[nt][1] + b1);
                        float2 o;
                        o.x = (1.f - z0) * nn[nt][0] + z0 * h.x;
                        o.y = (1.f - z1) * nn[nt][1] + z1 * h.y;
                        *(float2*)hp = o;
                        ((uint32_t*)hnxt)[((size_t)gr1 * HIDDEN + coli) >> 1] = bf2(o.x, o.y);
                    }
                    if (gr2 < N_NODES) {
                        float* hp = d_h + (size_t)gr2 * HIDDEN + coli;
                        float2 h = *(float2*)hp;
                        float z0 = sigm_f(ci[nt][2] + b0), z1 = sigm_f(ci[nt][3] + b1);
                        float2 o;
                        o.x = (1.f - z0) * nn[nt][2] + z0 * h.x;
                        o.y = (1.f - z1) * nn[nt][3] + z1 * h.y;
                        *(float2*)hp = o;
                        ((uint32_t*)hnxt)[((size_t)gr2 * HIDDEN + coli) >> 1] = bf2(o.x, o.y);
                    }
                }
            }
        }
    }
}

// ---------------- Wcomb precompute: bf16( wih[g*128+n][:] . ggnn[l][k][:] ) ----------------
__global__ void __launch_bounds__(256) k_wcomb(const float* __restrict__ wih,
                                               const float* __restrict__ ggnn) {
    __shared__ float As[16][128];
    __shared__ float Bs[16][128];
    const float* A = wih + (size_t)blockIdx.x * 128 * HIDDEN;
    const float* B = ggnn + (size_t)blockIdx.y * HIDDEN * HIDDEN;
    __nv_bfloat16* C = d_Wcomb_bf + ((size_t)blockIdx.y * 3 + blockIdx.x) * 128 * HIDDEN;
    const int tid = threadIdx.x, tx = tid & 15, ty = tid >> 4;

    float acc[8][8];
#pragma unroll
    for (int i = 0; i < 8; i++)
#pragma unroll
        for (int j = 0; j < 8; j++) acc[i][j] = 0.f;

    for (int j0 = 0; j0 < 128; j0 += 16) {
#pragma unroll
        for (int q = tid; q < 512; q += 256) {
            int n = q >> 2, j4 = (q & 3) << 2;
            float4 va = *(const float4*)(A + (size_t)n * HIDDEN + j0 + j4);
            As[j4 + 0][n] = va.x; As[j4 + 1][n] = va.y;
            As[j4 + 2][n] = va.z; As[j4 + 3][n] = va.w;
            float4 vb = *(const float4*)(B + (size_t)n * HIDDEN + j0 + j4);
            Bs[j4 + 0][n] = vb.x; Bs[j4 + 1][n] = vb.y;
            Bs[j4 + 2][n] = vb.z; Bs[j4 + 3][n] = vb.w;
        }
        __syncthreads();
#pragma unroll
        for (int jj = 0; jj < 16; jj++) {
            float a[8], b[8];
#pragma unroll
            for (int i = 0; i < 8; i++) a[i] = As[jj][ty * 8 + i];
#pragma unroll
            for (int j = 0; j < 8; j++) b[j] = Bs[jj][tx * 8 + j];
#pragma unroll
            for (int i = 0; i < 8; i++)
#pragma unroll
                for (int j = 0; j < 8; j++) acc[i][j] = fmaf(a[i], b[j], acc[i][j]);
        }
        __syncthreads();
    }
#pragma unroll
    for (int i = 0; i < 8; i++)
#pragma unroll
        for (int j = 0; j < 8; j++)
            C[(size_t)(ty * 8 + i) * HIDDEN + tx * 8 + j] = __float2bfloat16(acc[i][j]);
}

__global__ void k_whh_bf(const float* __restrict__ whh) {
    int i = blockIdx.x * blockDim.x + threadIdx.x;  // < 49152
    d_whh_bf[i] = __float2bfloat16(whh[i]);
}

// ---------------- HMMA tf32 GEMM tile (fc1), 256 thr, occ 2 ----------------
template <bool HASBIAS>
__device__ __forceinline__ void hmma_tile(
    const float* __restrict__ A, const float* __restrict__ Bt,
    const float* __restrict__ bias, float* __restrict__ C, int ldc, int ccol0)
{
    __shared__ uint32_t As[128 * ASTRIDE];
    __shared__ uint32_t Bs[128 * ASTRIDE];
    const int tid = threadIdx.x, lane = tid & 31, w = tid >> 5;
    const int wm = w & 3, wn = w >> 2;
    const int gid = lane >> 2, tg = lane & 3;
    const int row0 = blockIdx.x * 128;

    float c[2][8][4];
#pragma unroll
    for (int i = 0; i < 2; i++)
#pragma unroll
        for (int j = 0; j < 8; j++)
#pragma unroll
            for (int q = 0; q < 4; q++) c[i][j][q] = 0.f;

#pragma unroll
    for (int kp = 0; kp < 4; kp++) {
        if (kp) __syncthreads();
#pragma unroll
        for (int q = tid; q < 1024; q += 256) {
            int r = q >> 3, k4 = (q & 7) << 2;
            int gr = row0 + r;
            if (gr >= N_NODES) gr = N_NODES - 1;
            float4 va = *(const float4*)(A + (size_t)gr * HIDDEN + kp * 32 + k4);
            *(uint4*)(As + r * ASTRIDE + k4) =
                make_uint4(f2tf32(va.x), f2tf32(va.y), f2tf32(va.z), f2tf32(va.w));
            float4 vb = *(const float4*)(Bt + (size_t)r * HIDDEN + kp * 32 + k4);
            *(uint4*)(Bs + r * ASTRIDE + k4) =
                make_uint4(f2tf32(vb.x), f2tf32(vb.y), f2tf32(vb.z), f2tf32(vb.w));
        }
        __syncthreads();
#pragma unroll
        for (int ks = 0; ks < 4; ks++) {
            int k0 = ks * 8;
            uint32_t af[2][4];
#pragma unroll
            for (int mt = 0; mt < 2; mt++) {
                int rb = wm * 32 + mt * 16;
                af[mt][0] = As[(rb + gid) * ASTRIDE + k0 + tg];
                af[mt][1] = As[(rb + gid + 8) * ASTRIDE + k0 + tg];
                af[mt][2] = As[(rb + gid) * ASTRIDE + k0 + tg + 4];
                af[mt][3] = As[(rb + gid + 8) * ASTRIDE + k0 + tg + 4];
            }
#pragma unroll
            for (int nt = 0; nt < 8; nt++) {
                uint32_t bf[2];
                int nb = wn * 64 + nt * 8 + gid;
                bf[0] = Bs[nb * ASTRIDE + k0 + tg];
                bf[1] = Bs[nb * ASTRIDE + k0 + tg + 4];
#pragma unroll
                for (int mt = 0; mt < 2; mt++) mma_tf32(c[mt][nt], af[mt], bf);
            }
        }
    }

#pragma unroll
    for (int mt = 0; mt < 2; mt++) {
        int r1 = row0 + wm * 32 + mt * 16 + gid;
        int r2 = r1 + 8;
#pragma unroll
        for (int nt = 0; nt < 8; nt++) {
            int coli = wn * 64 + nt * 8 + tg * 2;
            float b0 = 0.f, b1 = 0.f;
            if (HASBIAS) { b0 = bias[coli]; b1 = bias[coli + 1]; }
            if (r1 < N_NODES) {
                float2 v = make_float2(c[mt][nt][0] + b0, c[mt][nt][1] + b1);
                *(float2*)(C + (size_t)r1 * ldc + ccol0 + coli) = v;
            }
            if (r2 < N_NODES) {
                float2 v = make_float2(c[mt][nt][2] + b0, c[mt][nt][3] + b1);
                *(float2*)(C + (size_t)r2 * ldc + ccol0 + coli) = v;
            }
        }
    }
}

__global__ void __launch_bounds__(256, 2) k_mma_fc1(
    const float* __restrict__ w, const float* __restrict__ b) {
    hmma_tile<true>(d_h, w, b, d_m, HIDDEN, 0);
}

// ---------------- setup kernels ----------------
__global__ void k_init() {
    int i = blockIdx.x * blockDim.x + threadIdx.x;
    if (i < N_NODES) d_deg[i] = 0;
    if (i < NUM_GRAPHS * HIDDEN) d_pool[i] = 0.f;
    if (i < NUM_GRAPHS) d_cnt[i] = 0;
    if (i < HIDDEN) { d_sum[i] = 0.f; d_sumsq[i] = 0.f; }
}

__global__ void k_copy_x(const float* __restrict__ x) {
    int i = blockIdx.x * blockDim.x + threadIdx.x;  // 3.2M float4
    float4 v = ((const float4*)x)[i];
    ((float4*)d_h)[i] = v;
    ((uint2*)d_h_bf0)[i] = make_uint2(bf2(v.x, v.y), bf2(v.z, v.w));
}

__global__ void k_edges(const int* __restrict__ e) {
    int i = blockIdx.x * blockDim.x + threadIdx.x;
    int s = e[i];
    int d = e[N_EDGES + i];
    d_src[i] = s;
    d_dst[i] = d;
    atomicAdd(&d_deg[d], 1);
}

__global__ void k_batch_hist(const int* __restrict__ batch) {
    __shared__ int hc[NUM_GRAPHS];
    for (int i = threadIdx.x; i < NUM_GRAPHS; i += blockDim.x) hc[i] = 0;
    __syncthreads();
    int idx = blockIdx.x * blockDim.x + threadIdx.x;
    if (idx < N_NODES) atomicAdd(&hc[batch[idx]], 1);
    __syncthreads();
    for (int i = threadIdx.x; i < NUM_GRAPHS; i += blockDim.x)
        if (hc[i]) atomicAdd(&d_cnt[i], hc[i]);
}

__global__ void k_scan1() {
    __shared__ int sh[32];
    int lane = threadIdx.x & 31, warp = threadIdx.x >> 5;
    int idx = blockIdx.x * 1024 + threadIdx.x;
    int v = (idx < N_NODES) ? d_deg[idx] : 0;
#pragma unroll
    for (int o = 16; o; o >>= 1) v += __shfl_down_sync(0xFFFFFFFFu, v, o);
    if (lane == 0) sh[warp] = v;
    __syncthreads();
    if (warp == 0) {
        v = sh[lane];
#pragma unroll
        for (int o = 16; o; o >>= 1) v += __shfl_down_sync(0xFFFFFFFFu, v, o);
        if (lane == 0) d_blocksum[blockIdx.x] = v;
    }
}

__global__ void k_scan2() {
    __shared__ int s[128];
    int t = threadIdx.x;
    int v = (t < 98) ? d_blocksum[t] : 0;
    s[t] = v;
    __syncthreads();
#pragma unroll
    for (int o = 1; o < 128; o <<= 1) {
        int tmp = (t >= o) ? s[t - o] : 0;
        __syncthreads();
        s[t] += tmp;
        __syncthreads();
    }
    if (t < 98) d_blockoff[t] = s[t] - v;
    if (t == 0) d_rowptr[N_NODES] = s[97];
}

__global__ void k_scan3() {
    __shared__ int s[1024];
    int t = threadIdx.x;
    int idx = blockIdx.x * 1024 + t;
    int v = (idx < N_NODES) ? d_deg[idx] : 0;
    s[t] = v;
    __syncthreads();
#pragma unroll
    for (int o = 1; o < 1024; o <<= 1) {
        int tmp = (t >= o) ? s[t - o] : 0;
        __syncthreads();
        s[t] += tmp;
        __syncthreads();
    }
    if (idx < N_NODES) {
        int ex = d_blockoff[blockIdx.x] + s[t] - v;
        d_rowptr[idx] = ex;
        d_cursor[idx] = ex;
    }
}

__global__ void k_csr_fill() {
    int i = blockIdx.x * blockDim.x + threadIdx.x;
    int pos = atomicAdd(&d_cursor[d_dst[i]], 1);
    d_colidx[pos] = d_src[i];
}

// ---------------- batchnorm + relu + mean pool + classifier ----------------
__global__ void k_bn_stats() {
    int c = threadIdx.x;
    int n0 = blockIdx.x * 500;
    int n1 = n0 + 500;
    float s = 0.f, s2 = 0.f;
    for (int n = n0; n < n1; n++) {
        float v = d_m[(size_t)n * HIDDEN + c];
        s += v;
        s2 += v * v;
    }
    atomicAdd(&d_sum[c], s);
    atomicAdd(&d_sumsq[c], s2);
}

__global__ void k_bn_final() {
    int c = threadIdx.x;
    float mu = d_sum[c] / (float)N_NODES;
    float var = d_sumsq[c] / (float)N_NODES - mu * mu;
    d_mean[c] = mu;
    d_rstd[c] = rsqrtf(var + BN_EPS);
}

__global__ void k_pool(const int* __restrict__ batch,
                       const float* __restrict__ gamma,
                       const float* __restrict__ beta) {
    int c = threadIdx.x;
    int n0 = blockIdx.x * 512;
    int n1 = n0 + 512;
    if (n1 > N_NODES) n1 = N_NODES;
    if (n0 >= N_NODES) return;
    float sc = gamma[c] * d_rstd[c];
    float mu = d_mean[c];
    float be = beta[c];
    float acc = 0.f;
    int cur = batch[n0];
    for (int n = n0; n < n1; n++) {
        int bb = batch[n];
        if (bb != cur) {
            atomicAdd(&d_pool[cur * HIDDEN + c], acc);
            acc = 0.f;
            cur = bb;
        }
        float v = (d_m[(size_t)n * HIDDEN + c] - mu) * sc + be;
        acc += fmaxf(v, 0.f);
    }
    atomicAdd(&d_pool[cur * HIDDEN + c], acc);
}

__global__ void k_final(const float* __restrict__ w2, const float* __restrict__ b2,
                        float* __restrict__ out) {
    __shared__ float sf[HIDDEN];
    __shared__ float lg[NUM_CLASSES];
    int g = blockIdx.x, t = threadIdx.x;
    float cnt = fmaxf((float)d_cnt[g], 1.f);
    sf[t] = d_pool[g * HIDDEN + t] / cnt;
    __syncthreads();
    if (t < NUM_CLASSES) {
        float s = b2[t];
        for (int k = 0; k < HIDDEN; k++) s += sf[k] * w2[t * HIDDEN + k];
        lg[t] = s;
    }
    __syncthreads();
    if (t == 0) {
        float mx = -1e30f;
        for (int c = 0; c < NUM_CLASSES; c++) mx = fmaxf(mx, lg[c]);
        float se = 0.f;
        for (int c = 0; c < NUM_CLASSES; c++) se += expf(lg[c] - mx);
        float lse = mx + logf(se);
        for (int c = 0; c < NUM_CLASSES; c++) out[g * NUM_CLASSES + c] = lg[c] - lse;
    }
}

// ---------------- launch ----------------
extern "C" void kernel_launch(void* const* d_in, const int* in_sizes, int n_in,
                              void* d_out, int out_size) {
    const float* x     = (const float*)d_in[0];
    const int*   ei    = (const int*)d_in[1];
    const int*   bat   = (const int*)d_in[2];
    const float* ggnn  = (const float*)d_in[3];
    const float* wih   = (const float*)d_in[4];
    const float* whh   = (const float*)d_in[5];
    const float* bih   = (const float*)d_in[6];
    const float* bhh   = (const float*)d_in[7];
    const float* fc1w  = (const float*)d_in[8];
    const float* fc1b  = (const float*)d_in[9];
    const float* gamma = (const float*)d_in[10];
    const float* beta  = (const float*)d_in[11];
    const float* fc2w  = (const float*)d_in[12];
    const float* fc2b  = (const float*)d_in[13];
    float* out = (float*)d_out;

    cudaFuncSetAttribute(k_gru_fused, cudaFuncAttributeMaxDynamicSharedMemorySize,
                         GRU_SMEM_BYTES);

    k_init<<<(N_NODES + 255) / 256, 256>>>();
    k_copy_x<<<(N_NODES * HIDDEN / 4) / 256, 256>>>(x);
    k_edges<<<N_EDGES / 256, 256>>>(ei);
    k_batch_hist<<<98, 1024>>>(bat);
    k_scan1<<<98, 1024>>>();
    k_scan2<<<1, 128>>>();
    k_scan3<<<98, 1024>>>();
    k_csr_fill<<<N_EDGES / 256, 256>>>();
    k_wcomb<<<dim3(3, NUM_LAYERS), 256>>>(wih, ggnn);
    k_whh_bf<<<192, 256>>>(whh);

    const int gru_blocks = (N_NODES + 63) / 64;  // 1563
    for (int l = 0; l < NUM_LAYERS; l++) {
        k_gru_fused<<<gru_blocks, 512, GRU_SMEM_BYTES>>>(l, l & 1, bih, bhh);
    }

    k_mma_fc1<<<(N_NODES + 127) / 128, 256>>>(fc1w, fc1b);
    k_bn_stats<<<200, 128>>>();
    k_bn_final<<<1, 128>>>();
    k_pool<<<(N_NODES + 511) / 512, 128>>>(bat, gamma, beta);
    k_final<<<NUM_GRAPHS, 128>>>(fc2w, fc2b, out);
}

// round 11
// speedup vs baseline: 1.0913x; 1.0913x over previous
#include <cuda_runtime.h>
#include <cuda_bf16.h>
#include <cstdint>

#define N_NODES 100000
#define N_EDGES 1600000
#define HIDDEN 128
#define NUM_CLASSES 10
#define NUM_LAYERS 4
#define NUM_GRAPHS 200
#define BN_EPS 1e-5f

// ---------------- scratch (static device arrays: no allocations) ----------------
__device__ float d_h[(size_t)N_NODES * HIDDEN];            // exact fp32 state
__device__ __nv_bfloat16 d_h_bf[(size_t)N_NODES * HIDDEN]; // bf16 mirror (gather source)
__device__ __nv_bfloat16 d_agg_bf[(size_t)N_NODES * HIDDEN];
__device__ float d_m[(size_t)N_NODES * HIDDEN];            // fc1 output
__device__ __nv_bfloat16 d_Wcomb_bf[NUM_LAYERS * 3 * HIDDEN * HIDDEN];
__device__ __nv_bfloat16 d_whh_bf[3 * HIDDEN * HIDDEN];
__device__ int d_src[N_EDGES];
__device__ int d_dst[N_EDGES];
__device__ int d_deg[N_NODES];
__device__ int d_rowptr[N_NODES + 1];
__device__ int d_cursor[N_NODES];
__device__ int d_colidx[N_EDGES];
__device__ int d_blocksum[128];
__device__ int d_blockoff[128];
__device__ float d_sum[HIDDEN], d_sumsq[HIDDEN], d_mean[HIDDEN], d_rstd[HIDDEN];
__device__ float d_pool[NUM_GRAPHS * HIDDEN];
__device__ int d_cnt[NUM_GRAPHS];

// ---------------- helpers ----------------
__device__ __forceinline__ float sigm_f(float x) {
    return __fdividef(1.f, 1.f + __expf(-x));
}
__device__ __forceinline__ float tanh_f(float x) {
    return 1.f - __fdividef(2.f, __expf(2.f * x) + 1.f);
}
__device__ __forceinline__ uint32_t smem_u32(const void* p) {
    uint32_t a;
    asm("{ .reg .u64 t; cvta.to.shared.u64 t, %1; cvt.u32.u64 %0, t; }" : "=r"(a) : "l"(p));
    return a;
}
__device__ __forceinline__ uint32_t f2tf32(float f) {
    uint32_t r;
    asm("cvt.rna.tf32.f32 %0, %1;" : "=r"(r) : "f"(f));
    return r;
}
__device__ __forceinline__ uint32_t bf2(float lo, float hi) {
    __nv_bfloat162 p = __floats2bfloat162_rn(lo, hi);
    return *(uint32_t*)&p;
}
__device__ __forceinline__ void mma_tf32(float* c, const uint32_t* a, const uint32_t* b) {
    asm volatile(
        "mma.sync.aligned.m16n8k8.row.col.f32.tf32.tf32.f32 "
        "{%0,%1,%2,%3}, {%4,%5,%6,%7}, {%8,%9}, {%0,%1,%2,%3};"
        : "+f"(c[0]), "+f"(c[1]), "+f"(c[2]), "+f"(c[3])
        : "r"(a[0]), "r"(a[1]), "r"(a[2]), "r"(a[3]), "r"(b[0]), "r"(b[1]));
}
__device__ __forceinline__ void mma_bf16(float* c, const uint32_t* a, const uint32_t* b) {
    asm volatile(
        "mma.sync.aligned.m16n8k16.row.col.f32.bf16.bf16.f32 "
        "{%0,%1,%2,%3}, {%4,%5,%6,%7}, {%8,%9}, {%0,%1,%2,%3};"
        : "+f"(c[0]), "+f"(c[1]), "+f"(c[2]), "+f"(c[3])
        : "r"(a[0]), "r"(a[1]), "r"(a[2]), "r"(a[3]), "r"(b[0]), "r"(b[1]));
}
__device__ __forceinline__ void cpasync16(uint32_t daddr, const void* src, int srcbytes) {
    asm volatile("cp.async.cg.shared.global [%0], [%1], 16, %2;"
                 :: "r"(daddr), "l"(src), "r"(srcbytes));
}
__device__ __forceinline__ void cpasync_commit() {
    asm volatile("cp.async.commit_group;" ::: "memory");
}

#define ASTRIDE 36
// gru smem (uint32 words, each = one bf16x2): A [64 rows][132], B 4 x [128][36]
#define S2A 132
#define S2B 36
#define AS_W (64 * S2A)
#define BS_W (128 * S2B)
#define NBUF 4
#define GRU_SMEM_BYTES ((AS_W + NBUF * BS_W) * 4)  // 107520 B -> 2 CTAs/SM (210 KB)

// ============ fused GRU layer (bf16 MMA): 64 rows/block, 512 thr, 4-deep cp.async ============
// Gate g: out = hsum @ Wcomb_g^T + h @ Whh_g^T (K=256 = 4 sub-chunks of 64 halves).
// 12 chunks: pass R(g=0) 0-3, N(g=2) 4-7, Z(g=1) 8-11.
__device__ __forceinline__ void gru_issueB(uint32_t bufaddr, const __nv_bfloat16* __restrict__ wcomb,
                                           int chunk, int tid) {
    int pass = chunk >> 2;
    int g = (pass == 0) ? 0 : (pass == 1) ? 2 : 1;
    int sub = chunk & 3;
    const __nv_bfloat16* base = ((sub < 2) ? wcomb : d_whh_bf) +
                                (size_t)g * 128 * HIDDEN + (sub & 1) * 64;
#pragma unroll
    for (int q = tid; q < 1024; q += 512) {
        int n = q >> 3, o = q & 7;
        cpasync16(bufaddr + (n * S2B + o * 4) * 4, base + (size_t)n * HIDDEN + o * 8, 16);
    }
    cpasync_commit();
}

__global__ void __launch_bounds__(512, 1) k_gru_fused(
    int layer, const float* __restrict__ bih, const float* __restrict__ bhh)
{
    extern __shared__ uint32_t dsm[];
    const __nv_bfloat16* wcomb = d_Wcomb_bf + (size_t)layer * 3 * HIDDEN * HIDDEN;
    const uint32_t sb = smem_u32(dsm);
    const uint32_t sbB = sb + AS_W * 4;

    const int tid = threadIdx.x, lane = tid & 31, w = tid >> 5;
    const int wm = w & 3, wn = w >> 2;  // 4 m-strips x 4 n-strips
    const int gid = lane >> 2, tg = lane & 3;
    const int row0 = blockIdx.x * 64;
    const int lr1 = wm * 16 + gid, lr2 = lr1 + 8;

    // ---- prologue: async-stage A tile ([agg_bf | h_bf], 64x256 halves) + chunks 0,1,2 ----
#pragma unroll
    for (int q = tid; q < 2048; q += 512) {
        int r = q >> 5, o = q & 31;  // 32 x 16B per row (16 agg + 16 h)
        int gr = row0 + r;
        int ok = (gr < N_NODES);
        if (!ok) gr = 0;
        const __nv_bfloat16* src = (o < 16) ? d_agg_bf + (size_t)gr * HIDDEN + o * 8
                                            : d_h_bf + (size_t)gr * HIDDEN + (o - 16) * 8;
        cpasync16(sb + (r * S2A + o * 4) * 4, src, ok ? 16 : 0);
    }
    gru_issueB(sbB, wcomb, 0, tid);                     // A + B0 in one group
    gru_issueB(sbB + BS_W * 4, wcomb, 1, tid);          // B1
    gru_issueB(sbB + 2 * BS_W * 4, wcomb, 2, tid);      // B2

    float rr[4][4], nn[4][4], ci[4][4], ch[4][4];
#pragma unroll
    for (int j = 0; j < 4; j++)
#pragma unroll
        for (int q = 0; q < 4; q++) { ci[j][q] = 0.f; ch[j][q] = 0.f; }

    for (int it = 0; it < 12; it++) {
        // groups issued so far: 0..min(it+2, 11). Need group it complete.
        if (it < 10) asm volatile("cp.async.wait_group 2;" ::: "memory");
        else if (it == 10) asm volatile("cp.async.wait_group 1;" ::: "memory");
        else asm volatile("cp.async.wait_group 0;" ::: "memory");
        __syncthreads();

        if (it + 3 < 12) gru_issueB(sbB + ((it + 3) & 3) * BS_W * 4, wcomb, it + 3, tid);

        const uint32_t* BS = dsm + AS_W + (it & 3) * BS_W;
        const int pass = it >> 2, sub = it & 3;
        float(*acc)[4] = (pass == 1 && sub >= 2) ? ch : ci;
        const int kbase = sub * 32;  // half2 units
#pragma unroll
        for (int ks = 0; ks < 4; ks++) {
            int kb = kbase + ks * 8;
            uint32_t af[4];
            af[0] = dsm[lr1 * S2A + kb + tg];
            af[1] = dsm[lr2 * S2A + kb + tg];
            af[2] = dsm[lr1 * S2A + kb + tg + 4];
            af[3] = dsm[lr2 * S2A + kb + tg + 4];
#pragma unroll
            for (int nt = 0; nt < 4; nt++) {
                uint32_t bf[2];
                int nb = wn * 32 + nt * 8 + gid;
                bf[0] = BS[nb * S2B + ks * 8 + tg];
                bf[1] = BS[nb * S2B + ks * 8 + tg + 4];
                mma_bf16(acc[nt], af, bf);
            }
        }

        if (sub == 3) {
            if (pass == 0) {  // R
#pragma unroll
                for (int nt = 0; nt < 4; nt++) {
                    int coli = wn * 32 + nt * 8 + tg * 2;
                    float b0 = bih[coli] + bhh[coli];
                    float b1 = bih[coli + 1] + bhh[coli + 1];
                    rr[nt][0] = sigm_f(ci[nt][0] + b0);
                    rr[nt][1] = sigm_f(ci[nt][1] + b1);
                    rr[nt][2] = sigm_f(ci[nt][2] + b0);
                    rr[nt][3] = sigm_f(ci[nt][3] + b1);
#pragma unroll
                    for (int q = 0; q < 4; q++) ci[nt][q] = 0.f;
                }
            } else if (pass == 1) {  // N
#pragma unroll
                for (int nt = 0; nt < 4; nt++) {
                    int coli = wn * 32 + nt * 8 + tg * 2;
                    float bi0 = bih[256 + coli], bi1 = bih[256 + coli + 1];
                    float bh0 = bhh[256 + coli], bh1 = bhh[256 + coli + 1];
                    nn[nt][0] = tanh_f(ci[nt][0] + bi0 + rr[nt][0] * (ch[nt][0] + bh0));
                    nn[nt][1] = tanh_f(ci[nt][1] + bi1 + rr[nt][1] * (ch[nt][1] + bh1));
                    nn[nt][2] = tanh_f(ci[nt][2] + bi0 + rr[nt][2] * (ch[nt][2] + bh0));
                    nn[nt][3] = tanh_f(ci[nt][3] + bi1 + rr[nt][3] * (ch[nt][3] + bh1));
#pragma unroll
                    for (int q = 0; q < 4; q++) ci[nt][q] = 0.f;
                }
            } else {  // Z + in-place h update (fp32 + bf16 mirror)
                int gr1 = row0 + lr1, gr2 = row0 + lr2;
#pragma unroll
                for (int nt = 0; nt < 4; nt++) {
                    int coli = wn * 32 + nt * 8 + tg * 2;
                    float b0 = bih[128 + coli] + bhh[128 + coli];
                    float b1 = bih[128 + coli + 1] + bhh[128 + coli + 1];
                    if (gr1 < N_NODES) {
                        float* hp = d_h + (size_t)gr1 * HIDDEN + coli;
                        float2 h = *(float2*)hp;
                        float z0 = sigm_f(ci[nt][0] + b0), z1 = sigm_f(ci[nt][1] + b1);
                        float2 o;
                        o.x = (1.f - z0) * nn[nt][0] + z0 * h.x;
                        o.y = (1.f - z1) * nn[nt][1] + z1 * h.y;
                        *(float2*)hp = o;
                        ((uint32_t*)d_h_bf)[((size_t)gr1 * HIDDEN + coli) >> 1] = bf2(o.x, o.y);
                    }
                    if (gr2 < N_NODES) {
                        float* hp = d_h + (size_t)gr2 * HIDDEN + coli;
                        float2 h = *(float2*)hp;
                        float z0 = sigm_f(ci[nt][2] + b0), z1 = sigm_f(ci[nt][3] + b1);
                        float2 o;
                        o.x = (1.f - z0) * nn[nt][2] + z0 * h.x;
                        o.y = (1.f - z1) * nn[nt][3] + z1 * h.y;
                        *(float2*)hp = o;
                        ((uint32_t*)d_h_bf)[((size_t)gr2 * HIDDEN + coli) >> 1] = bf2(o.x, o.y);
                    }
                }
            }
        }
    }
}

// ---------------- Wcomb precompute: bf16( wih[g*128+n][:] . ggnn[l][k][:] ) ----------------
__global__ void __launch_bounds__(256) k_wcomb(const float* __restrict__ wih,
                                               const float* __restrict__ ggnn) {
    __shared__ float As[16][128];
    __shared__ float Bs[16][128];
    const float* A = wih + (size_t)blockIdx.x * 128 * HIDDEN;
    const float* B = ggnn + (size_t)blockIdx.y * HIDDEN * HIDDEN;
    __nv_bfloat16* C = d_Wcomb_bf + ((size_t)blockIdx.y * 3 + blockIdx.x) * 128 * HIDDEN;
    const int tid = threadIdx.x, tx = tid & 15, ty = tid >> 4;

    float acc[8][8];
#pragma unroll
    for (int i = 0; i < 8; i++)
#pragma unroll
        for (int j = 0; j < 8; j++) acc[i][j] = 0.f;

    for (int j0 = 0; j0 < 128; j0 += 16) {
#pragma unroll
        for (int q = tid; q < 512; q += 256) {
            int n = q >> 2, j4 = (q & 3) << 2;
            float4 va = *(const float4*)(A + (size_t)n * HIDDEN + j0 + j4);
            As[j4 + 0][n] = va.x; As[j4 + 1][n] = va.y;
            As[j4 + 2][n] = va.z; As[j4 + 3][n] = va.w;
            float4 vb = *(const float4*)(B + (size_t)n * HIDDEN + j0 + j4);
            Bs[j4 + 0][n] = vb.x; Bs[j4 + 1][n] = vb.y;
            Bs[j4 + 2][n] = vb.z; Bs[j4 + 3][n] = vb.w;
        }
        __syncthreads();
#pragma unroll
        for (int jj = 0; jj < 16; jj++) {
            float a[8], b[8];
#pragma unroll
            for (int i = 0; i < 8; i++) a[i] = As[jj][ty * 8 + i];
#pragma unroll
            for (int j = 0; j < 8; j++) b[j] = Bs[jj][tx * 8 + j];
#pragma unroll
            for (int i = 0; i < 8; i++)
#pragma unroll
                for (int j = 0; j < 8; j++) acc[i][j] = fmaf(a[i], b[j], acc[i][j]);
        }
        __syncthreads();
    }
#pragma unroll
    for (int i = 0; i < 8; i++)
#pragma unroll
        for (int j = 0; j < 8; j++)
            C[(size_t)(ty * 8 + i) * HIDDEN + tx * 8 + j] = __float2bfloat16(acc[i][j]);
}

__global__ void k_whh_bf(const float* __restrict__ whh) {
    int i = blockIdx.x * blockDim.x + threadIdx.x;  // < 49152
    d_whh_bf[i] = __float2bfloat16(whh[i]);
}

// ---------------- HMMA tf32 GEMM tile (fc1), 256 thr, occ 2 ----------------
template <bool HASBIAS>
__device__ __forceinline__ void hmma_tile(
    const float* __restrict__ A, const float* __restrict__ Bt,
    const float* __restrict__ bias, float* __restrict__ C, int ldc, int ccol0)
{
    __shared__ uint32_t As[128 * ASTRIDE];
    __shared__ uint32_t Bs[128 * ASTRIDE];
    const int tid = threadIdx.x, lane = tid & 31, w = tid >> 5;
    const int wm = w & 3, wn = w >> 2;
    const int gid = lane >> 2, tg = lane & 3;
    const int row0 = blockIdx.x * 128;

    float c[2][8][4];
#pragma unroll
    for (int i = 0; i < 2; i++)
#pragma unroll
        for (int j = 0; j < 8; j++)
#pragma unroll
            for (int q = 0; q < 4; q++) c[i][j][q] = 0.f;

#pragma unroll
    for (int kp = 0; kp < 4; kp++) {
        if (kp) __syncthreads();
#pragma unroll
        for (int q = tid; q < 1024; q += 256) {
            int r = q >> 3, k4 = (q & 7) << 2;
            int gr = row0 + r;
            if (gr >= N_NODES) gr = N_NODES - 1;
            float4 va = *(const float4*)(A + (size_t)gr * HIDDEN + kp * 32 + k4);
            *(uint4*)(As + r * ASTRIDE + k4) =
                make_uint4(f2tf32(va.x), f2tf32(va.y), f2tf32(va.z), f2tf32(va.w));
            float4 vb = *(const float4*)(Bt + (size_t)r * HIDDEN + kp * 32 + k4);
            *(uint4*)(Bs + r * ASTRIDE + k4) =
                make_uint4(f2tf32(vb.x), f2tf32(vb.y), f2tf32(vb.z), f2tf32(vb.w));
        }
        __syncthreads();
#pragma unroll
        for (int ks = 0; ks < 4; ks++) {
            int k0 = ks * 8;
            uint32_t af[2][4];
#pragma unroll
            for (int mt = 0; mt < 2; mt++) {
                int rb = wm * 32 + mt * 16;
                af[mt][0] = As[(rb + gid) * ASTRIDE + k0 + tg];
                af[mt][1] = As[(rb + gid + 8) * ASTRIDE + k0 + tg];
                af[mt][2] = As[(rb + gid) * ASTRIDE + k0 + tg + 4];
                af[mt][3] = As[(rb + gid + 8) * ASTRIDE + k0 + tg + 4];
            }
#pragma unroll
            for (int nt = 0; nt < 8; nt++) {
                uint32_t bf[2];
                int nb = wn * 64 + nt * 8 + gid;
                bf[0] = Bs[nb * ASTRIDE + k0 + tg];
                bf[1] = Bs[nb * ASTRIDE + k0 + tg + 4];
#pragma unroll
                for (int mt = 0; mt < 2; mt++) mma_tf32(c[mt][nt], af[mt], bf);
            }
        }
    }

#pragma unroll
    for (int mt = 0; mt < 2; mt++) {
        int r1 = row0 + wm * 32 + mt * 16 + gid;
        int r2 = r1 + 8;
#pragma unroll
        for (int nt = 0; nt < 8; nt++) {
            int coli = wn * 64 + nt * 8 + tg * 2;
            float b0 = 0.f, b1 = 0.f;
            if (HASBIAS) { b0 = bias[coli]; b1 = bias[coli + 1]; }
            if (r1 < N_NODES) {
                float2 v = make_float2(c[mt][nt][0] + b0, c[mt][nt][1] + b1);
                *(float2*)(C + (size_t)r1 * ldc + ccol0 + coli) = v;
            }
            if (r2 < N_NODES) {
                float2 v = make_float2(c[mt][nt][2] + b0, c[mt][nt][3] + b1);
                *(float2*)(C + (size_t)r2 * ldc + ccol0 + coli) = v;
            }
        }
    }
}

__global__ void __launch_bounds__(256, 2) k_mma_fc1(
    const float* __restrict__ w, const float* __restrict__ b) {
    hmma_tile<true>(d_h, w, b, d_m, HIDDEN, 0);
}

// ---------------- setup kernels ----------------
__global__ void k_init() {
    int i = blockIdx.x * blockDim.x + threadIdx.x;
    if (i < N_NODES) d_deg[i] = 0;
    if (i < NUM_GRAPHS * HIDDEN) d_pool[i] = 0.f;
    if (i < NUM_GRAPHS) d_cnt[i] = 0;
    if (i < HIDDEN) { d_sum[i] = 0.f; d_sumsq[i] = 0.f; }
}

__global__ void k_copy_x(const float* __restrict__ x) {
    int i = blockIdx.x * blockDim.x + threadIdx.x;  // 3.2M float4
    float4 v = ((const float4*)x)[i];
    ((float4*)d_h)[i] = v;
    ((uint2*)d_h_bf)[i] = make_uint2(bf2(v.x, v.y), bf2(v.z, v.w));
}

__global__ void k_edges(const int* __restrict__ e) {
    int i = blockIdx.x * blockDim.x + threadIdx.x;
    int s = e[i];
    int d = e[N_EDGES + i];
    d_src[i] = s;
    d_dst[i] = d;
    atomicAdd(&d_deg[d], 1);
}

__global__ void k_batch_hist(const int* __restrict__ batch) {
    __shared__ int hc[NUM_GRAPHS];
    for (int i = threadIdx.x; i < NUM_GRAPHS; i += blockDim.x) hc[i] = 0;
    __syncthreads();
    int idx = blockIdx.x * blockDim.x + threadIdx.x;
    if (idx < N_NODES) atomicAdd(&hc[batch[idx]], 1);
    __syncthreads();
    for (int i = threadIdx.x; i < NUM_GRAPHS; i += blockDim.x)
        if (hc[i]) atomicAdd(&d_cnt[i], hc[i]);
}

__global__ void k_scan1() {
    __shared__ int sh[32];
    int lane = threadIdx.x & 31, warp = threadIdx.x >> 5;
    int idx = blockIdx.x * 1024 + threadIdx.x;
    int v = (idx < N_NODES) ? d_deg[idx] : 0;
#pragma unroll
    for (int o = 16; o; o >>= 1) v += __shfl_down_sync(0xFFFFFFFFu, v, o);
    if (lane == 0) sh[warp] = v;
    __syncthreads();
    if (warp == 0) {
        v = sh[lane];
#pragma unroll
        for (int o = 16; o; o >>= 1) v += __shfl_down_sync(0xFFFFFFFFu, v, o);
        if (lane == 0) d_blocksum[blockIdx.x] = v;
    }
}

__global__ void k_scan2() {
    __shared__ int s[128];
    int t = threadIdx.x;
    int v = (t < 98) ? d_blocksum[t] : 0;
    s[t] = v;
    __syncthreads();
#pragma unroll
    for (int o = 1; o < 128; o <<= 1) {
        int tmp = (t >= o) ? s[t - o] : 0;
        __syncthreads();
        s[t] += tmp;
        __syncthreads();
    }
    if (t < 98) d_blockoff[t] = s[t] - v;
    if (t == 0) d_rowptr[N_NODES] = s[97];
}

__global__ void k_scan3() {
    __shared__ int s[1024];
    int t = threadIdx.x;
    int idx = blockIdx.x * 1024 + t;
    int v = (idx < N_NODES) ? d_deg[idx] : 0;
    s[t] = v;
    __syncthreads();
#pragma unroll
    for (int o = 1; o < 1024; o <<= 1) {
        int tmp = (t >= o) ? s[t - o] : 0;
        __syncthreads();
        s[t] += tmp;
        __syncthreads();
    }
    if (idx < N_NODES) {
        int ex = d_blockoff[blockIdx.x] + s[t] - v;
        d_rowptr[idx] = ex;
        d_cursor[idx] = ex;
    }
}

__global__ void k_csr_fill() {
    int i = blockIdx.x * blockDim.x + threadIdx.x;
    int pos = atomicAdd(&d_cursor[d_dst[i]], 1);
    d_colidx[pos] = d_src[i];
}

// ---------------- CSR aggregate of h (bf16): one warp per destination node ----------------
__global__ void k_aggregate() {
    int warp = (blockIdx.x * blockDim.x + threadIdx.x) >> 5;
    int lane = threadIdx.x & 31;
    if (warp >= N_NODES) return;
    int beg = d_rowptr[warp], end = d_rowptr[warp + 1];
    const uint2* hb = (const uint2*)d_h_bf;  // 32 uint2 per row
    float4 acc = make_float4(0.f, 0.f, 0.f, 0.f);
    for (int e = beg; e < end; e++) {
        int src = d_colidx[e];
        uint2 v = hb[(size_t)src * 32 + lane];
        float2 f0 = __bfloat1622float2(*(__nv_bfloat162*)&v.x);
        float2 f1 = __bfloat1622float2(*(__nv_bfloat162*)&v.y);
        acc.x += f0.x; acc.y += f0.y; acc.z += f1.x; acc.w += f1.y;
    }
    ((uint2*)d_agg_bf)[(size_t)warp * 32 + lane] =
        make_uint2(bf2(acc.x, acc.y), bf2(acc.z, acc.w));
}

// ---------------- batchnorm + relu + mean pool + classifier ----------------
__global__ void k_bn_stats() {
    int c = threadIdx.x;
    int n0 = blockIdx.x * 500;
    int n1 = n0 + 500;
    float s = 0.f, s2 = 0.f;
    for (int n = n0; n < n1; n++) {
        float v = d_m[(size_t)n * HIDDEN + c];
        s += v;
        s2 += v * v;
    }
    atomicAdd(&d_sum[c], s);
    atomicAdd(&d_sumsq[c], s2);
}

__global__ void k_bn_final() {
    int c = threadIdx.x;
    float mu = d_sum[c] / (float)N_NODES;
    float var = d_sumsq[c] / (float)N_NODES - mu * mu;
    d_mean[c] = mu;
    d_rstd[c] = rsqrtf(var + BN_EPS);
}

__global__ void k_pool(const int* __restrict__ batch,
                       const float* __restrict__ gamma,
                       const float* __restrict__ beta) {
    int c = threadIdx.x;
    int n0 = blockIdx.x * 512;
    int n1 = n0 + 512;
    if (n1 > N_NODES) n1 = N_NODES;
    if (n0 >= N_NODES) return;
    float sc = gamma[c] * d_rstd[c];
    float mu = d_mean[c];
    float be = beta[c];
    float acc = 0.f;
    int cur = batch[n0];
    for (int n = n0; n < n1; n++) {
        int bb = batch[n];
        if (bb != cur) {
            atomicAdd(&d_pool[cur * HIDDEN + c], acc);
            acc = 0.f;
            cur = bb;
        }
        float v = (d_m[(size_t)n * HIDDEN + c] - mu) * sc + be;
        acc += fmaxf(v, 0.f);
    }
    atomicAdd(&d_pool[cur * HIDDEN + c], acc);
}

__global__ void k_final(const float* __restrict__ w2, const float* __restrict__ b2,
                        float* __restrict__ out) {
    __shared__ float sf[HIDDEN];
    __shared__ float lg[NUM_CLASSES];
    int g = blockIdx.x, t = threadIdx.x;
    float cnt = fmaxf((float)d_cnt[g], 1.f);
    sf[t] = d_pool[g * HIDDEN + t] / cnt;
    __syncthreads();
    if (t < NUM_CLASSES) {
        float s = b2[t];
        for (int k = 0; k < HIDDEN; k++) s += sf[k] * w2[t * HIDDEN + k];
        lg[t] = s;
    }
    __syncthreads();
    if (t == 0) {
        float mx = -1e30f;
        for (int c = 0; c < NUM_CLASSES; c++) mx = fmaxf(mx, lg[c]);
        float se = 0.f;
        for (int c = 0; c < NUM_CLASSES; c++) se += expf(lg[c] - mx);
        float lse = mx + logf(se);
        for (int c = 0; c < NUM_CLASSES; c++) out[g * NUM_CLASSES + c] = lg[c] - lse;
    }
}

// ---------------- launch ----------------
extern "C" void kernel_launch(void* const* d_in, const int* in_sizes, int n_in,
                              void* d_out, int out_size) {
    const float* x     = (const float*)d_in[0];
    const int*   ei    = (const int*)d_in[1];
    const int*   bat   = (const int*)d_in[2];
    const float* ggnn  = (const float*)d_in[3];
    const float* wih   = (const float*)d_in[4];
    const float* whh   = (const float*)d_in[5];
    const float* bih   = (const float*)d_in[6];
    const float* bhh   = (const float*)d_in[7];
    const float* fc1w  = (const float*)d_in[8];
    const float* fc1b  = (const float*)d_in[9];
    const float* gamma = (const float*)d_in[10];
    const float* beta  = (const float*)d_in[11];
    const float* fc2w  = (const float*)d_in[12];
    const float* fc2b  = (const float*)d_in[13];
    float* out = (float*)d_out;

    cudaFuncSetAttribute(k_gru_fused, cudaFuncAttributeMaxDynamicSharedMemorySize,
                         GRU_SMEM_BYTES);

    k_init<<<(N_NODES + 255) / 256, 256>>>();
    k_copy_x<<<(N_NODES * HIDDEN / 4) / 256, 256>>>(x);
    k_edges<<<N_EDGES / 256, 256>>>(ei);
    k_batch_hist<<<98, 1024>>>(bat);
    k_scan1<<<98, 1024>>>();
    k_scan2<<<1, 128>>>();
    k_scan3<<<98, 1024>>>();
    k_csr_fill<<<N_EDGES / 256, 256>>>();
    k_wcomb<<<dim3(3, NUM_LAYERS), 256>>>(wih, ggnn);
    k_whh_bf<<<192, 256>>>(whh);

    const int gru_blocks = (N_NODES + 63) / 64;  // 1563
    for (int l = 0; l < NUM_LAYERS; l++) {
        k_aggregate<<<(N_NODES * 32) / 256, 256>>>();
        k_gru_fused<<<gru_blocks, 512, GRU_SMEM_BYTES>>>(l, bih, bhh);
    }

    k_mma_fc1<<<(N_NODES + 127) / 128, 256>>>(fc1w, fc1b);
    k_bn_stats<<<200, 128>>>();
    k_bn_final<<<1, 128>>>();
    k_pool<<<(N_NODES + 511) / 512, 128>>>(bat, gamma, beta);
    k_final<<<NUM_GRAPHS, 128>>>(fc2w, fc2b, out);
}

// round 14
// speedup vs baseline: 1.2196x; 1.1175x over previous
#include <cuda_runtime.h>
#include <cuda_bf16.h>
#include <cstdint>

#define N_NODES 100000
#define N_EDGES 1600000
#define HIDDEN 128
#define NUM_CLASSES 10
#define NUM_LAYERS 4
#define NUM_GRAPHS 200
#define BN_EPS 1e-5f

// ---------------- scratch (static device arrays: no allocations) ----------------
__device__ __nv_bfloat16 d_h_bf[(size_t)N_NODES * HIDDEN]; // node state (bf16 only)
__device__ __nv_bfloat16 d_agg_bf[(size_t)N_NODES * HIDDEN];
__device__ float d_m[(size_t)N_NODES * HIDDEN];            // fc1 output
__device__ __nv_bfloat16 d_Wcomb_bf[NUM_LAYERS * 3 * HIDDEN * HIDDEN];
__device__ __nv_bfloat16 d_whh_bf[3 * HIDDEN * HIDDEN];
__device__ int d_src[N_EDGES];
__device__ int d_dst[N_EDGES];
__device__ int d_deg[N_NODES];
__device__ int d_rowptr[N_NODES + 1];
__device__ int d_cursor[N_NODES];
__device__ int d_colidx[N_EDGES];
__device__ int d_blocksum[128];
__device__ int d_blockoff[128];
__device__ float d_sum[HIDDEN], d_sumsq[HIDDEN], d_mean[HIDDEN], d_rstd[HIDDEN];
__device__ float d_pool[NUM_GRAPHS * HIDDEN];
__device__ int d_cnt[NUM_GRAPHS];

// ---------------- helpers ----------------
__device__ __forceinline__ float sigm_f(float x) {
    return __fdividef(1.f, 1.f + __expf(-x));
}
__device__ __forceinline__ float tanh_f(float x) {
    return 1.f - __fdividef(2.f, __expf(2.f * x) + 1.f);
}
__device__ __forceinline__ uint32_t smem_u32(const void* p) {
    uint32_t a;
    asm("{ .reg .u64 t; cvta.to.shared.u64 t, %1; cvt.u32.u64 %0, t; }" : "=r"(a) : "l"(p));
    return a;
}
__device__ __forceinline__ uint32_t f2tf32(float f) {
    uint32_t r;
    asm("cvt.rna.tf32.f32 %0, %1;" : "=r"(r) : "f"(f));
    return r;
}
__device__ __forceinline__ uint32_t bf2(float lo, float hi) {
    __nv_bfloat162 p = __floats2bfloat162_rn(lo, hi);
    return *(uint32_t*)&p;
}
__device__ __forceinline__ void mma_tf32(float* c, const uint32_t* a, const uint32_t* b) {
    asm volatile(
        "mma.sync.aligned.m16n8k8.row.col.f32.tf32.tf32.f32 "
        "{%0,%1,%2,%3}, {%4,%5,%6,%7}, {%8,%9}, {%0,%1,%2,%3};"
        : "+f"(c[0]), "+f"(c[1]), "+f"(c[2]), "+f"(c[3])
        : "r"(a[0]), "r"(a[1]), "r"(a[2]), "r"(a[3]), "r"(b[0]), "r"(b[1]));
}
__device__ __forceinline__ void mma_bf16(float* c, const uint32_t* a, const uint32_t* b) {
    asm volatile(
        "mma.sync.aligned.m16n8k16.row.col.f32.bf16.bf16.f32 "
        "{%0,%1,%2,%3}, {%4,%5,%6,%7}, {%8,%9}, {%0,%1,%2,%3};"
        : "+f"(c[0]), "+f"(c[1]), "+f"(c[2]), "+f"(c[3])
        : "r"(a[0]), "r"(a[1]), "r"(a[2]), "r"(a[3]), "r"(b[0]), "r"(b[1]));
}
__device__ __forceinline__ void cpasync16(uint32_t daddr, const void* src, int srcbytes) {
    asm volatile("cp.async.cg.shared.global [%0], [%1], 16, %2;"
                 :: "r"(daddr), "l"(src), "r"(srcbytes));
}
__device__ __forceinline__ void cpasync_commit() {
    asm volatile("cp.async.commit_group;" ::: "memory");
}

#define ASTRIDE 36
// gru smem (uint32 words, each = one bf16x2): A [64 rows][132], B 4 x [128][36]
#define S2A 132
#define S2B 36
#define AS_W (64 * S2A)
#define BS_W (128 * S2B)
#define NBUF 4
#define GRU_SMEM_BYTES ((AS_W + NBUF * BS_W) * 4)  // 107520 B -> 2 CTAs/SM

// ============ fused GRU layer (bf16 MMA): 64 rows/block, 512 thr, 4-deep cp.async ============
// Gate g: out = hsum @ Wcomb_g^T + h @ Whh_g^T (K=256 = 4 sub-chunks of 64 halves).
// 12 chunks: pass R(g=0) 0-3, N(g=2) 4-7, Z(g=1) 8-11.
// h state is bf16-only; old h for the Z blend is read back from the smem A tile.
__device__ __forceinline__ void gru_issueB(uint32_t bufaddr, const __nv_bfloat16* __restrict__ wcomb,
                                           int chunk, int tid) {
    int pass = chunk >> 2;
    int g = (pass == 0) ? 0 : (pass == 1) ? 2 : 1;
    int sub = chunk & 3;
    const __nv_bfloat16* base = ((sub < 2) ? wcomb : d_whh_bf) +
                                (size_t)g * 128 * HIDDEN + (sub & 1) * 64;
#pragma unroll
    for (int q = tid; q < 1024; q += 512) {
        int n = q >> 3, o = q & 7;
        cpasync16(bufaddr + (n * S2B + o * 4) * 4, base + (size_t)n * HIDDEN + o * 8, 16);
    }
    cpasync_commit();
}

__global__ void __launch_bounds__(512, 1) k_gru_fused(
    int layer, const float* __restrict__ bih, const float* __restrict__ bhh)
{
    extern __shared__ uint32_t dsm[];
    const __nv_bfloat16* wcomb = d_Wcomb_bf + (size_t)layer * 3 * HIDDEN * HIDDEN;
    const uint32_t sb = smem_u32(dsm);
    const uint32_t sbB = sb + AS_W * 4;

    const int tid = threadIdx.x, lane = tid & 31, w = tid >> 5;
    const int wm = w & 3, wn = w >> 2;  // 4 m-strips x 4 n-strips
    const int gid = lane >> 2, tg = lane & 3;
    const int row0 = blockIdx.x * 64;
    const int lr1 = wm * 16 + gid, lr2 = lr1 + 8;

    // ---- prologue: async-stage A tile ([agg_bf | h_bf], 64x256 halves) + chunks 0,1,2 ----
#pragma unroll
    for (int q = tid; q < 2048; q += 512) {
        int r = q >> 5, o = q & 31;  // 32 x 16B per row (16 agg + 16 h)
        int gr = row0 + r;
        int ok = (gr < N_NODES);
        if (!ok) gr = 0;
        const __nv_bfloat16* src = (o < 16) ? d_agg_bf + (size_t)gr * HIDDEN + o * 8
                                            : d_h_bf + (size_t)gr * HIDDEN + (o - 16) * 8;
        cpasync16(sb + (r * S2A + o * 4) * 4, src, ok ? 16 : 0);
    }
    gru_issueB(sbB, wcomb, 0, tid);                     // A + B0 in one group
    gru_issueB(sbB + BS_W * 4, wcomb, 1, tid);          // B1
    gru_issueB(sbB + 2 * BS_W * 4, wcomb, 2, tid);      // B2

    float rr[4][4], nn[4][4], ci[4][4], ch[4][4];
#pragma unroll
    for (int j = 0; j < 4; j++)
#pragma unroll
        for (int q = 0; q < 4; q++) { ci[j][q] = 0.f; ch[j][q] = 0.f; }

    for (int it = 0; it < 12; it++) {
        if (it < 10) asm volatile("cp.async.wait_group 2;" ::: "memory");
        else if (it == 10) asm volatile("cp.async.wait_group 1;" ::: "memory");
        else asm volatile("cp.async.wait_group 0;" ::: "memory");
        __syncthreads();

        if (it + 3 < 12) gru_issueB(sbB + ((it + 3) & 3) * BS_W * 4, wcomb, it + 3, tid);

        const uint32_t* BS = dsm + AS_W + (it & 3) * BS_W;
        const int pass = it >> 2, sub = it & 3;
        float(*acc)[4] = (pass == 1 && sub >= 2) ? ch : ci;
        const int kbase = sub * 32;  // half2 units
#pragma unroll
        for (int ks = 0; ks < 4; ks++) {
            int kb = kbase + ks * 8;
            uint32_t af[4];
            af[0] = dsm[lr1 * S2A + kb + tg];
            af[1] = dsm[lr2 * S2A + kb + tg];
            af[2] = dsm[lr1 * S2A + kb + tg + 4];
            af[3] = dsm[lr2 * S2A + kb + tg + 4];
#pragma unroll
            for (int nt = 0; nt < 4; nt++) {
                uint32_t bf[2];
                int nb = wn * 32 + nt * 8 + gid;
                bf[0] = BS[nb * S2B + ks * 8 + tg];
                bf[1] = BS[nb * S2B + ks * 8 + tg + 4];
                mma_bf16(acc[nt], af, bf);
            }
        }

        if (sub == 3) {
            if (pass == 0) {  // R
#pragma unroll
                for (int nt = 0; nt < 4; nt++) {
                    int coli = wn * 32 + nt * 8 + tg * 2;
                    float b0 = bih[coli] + bhh[coli];
                    float b1 = bih[coli + 1] + bhh[coli + 1];
                    rr[nt][0] = sigm_f(ci[nt][0] + b0);
                    rr[nt][1] = sigm_f(ci[nt][1] + b1);
                    rr[nt][2] = sigm_f(ci[nt][2] + b0);
                    rr[nt][3] = sigm_f(ci[nt][3] + b1);
#pragma unroll
                    for (int q = 0; q < 4; q++) ci[nt][q] = 0.f;
                }
            } else if (pass == 1) {  // N
#pragma unroll
                for (int nt = 0; nt < 4; nt++) {
                    int coli = wn * 32 + nt * 8 + tg * 2;
                    float bi0 = bih[256 + coli], bi1 = bih[256 + coli + 1];
                    float bh0 = bhh[256 + coli], bh1 = bhh[256 + coli + 1];
                    nn[nt][0] = tanh_f(ci[nt][0] + bi0 + rr[nt][0] * (ch[nt][0] + bh0));
                    nn[nt][1] = tanh_f(ci[nt][1] + bi1 + rr[nt][1] * (ch[nt][1] + bh1));
                    nn[nt][2] = tanh_f(ci[nt][2] + bi0 + rr[nt][2] * (ch[nt][2] + bh0));
                    nn[nt][3] = tanh_f(ci[nt][3] + bi1 + rr[nt][3] * (ch[nt][3] + bh1));
#pragma unroll
                    for (int q = 0; q < 4; q++) ci[nt][q] = 0.f;
                }
            } else {  // Z: h_new = (1-z)*n + z*h_old; h_old read from smem A tile
                int gr1 = row0 + lr1, gr2 = row0 + lr2;
#pragma unroll
                for (int nt = 0; nt < 4; nt++) {
                    int coli = wn * 32 + nt * 8 + tg * 2;
                    int hword = 64 + (coli >> 1);  // h half of A row, bf16x2 word
                    float b0 = bih[128 + coli] + bhh[128 + coli];
                    float b1 = bih[128 + coli + 1] + bhh[128 + coli + 1];
                    if (gr1 < N_NODES) {
                        uint32_t hw = dsm[lr1 * S2A + hword];
                        float2 h = __bfloat1622float2(*(__nv_bfloat162*)&hw);
                        float z0 = sigm_f(ci[nt][0] + b0), z1 = sigm_f(ci[nt][1] + b1);
                        float ox = (1.f - z0) * nn[nt][0] + z0 * h.x;
                        float oy = (1.f - z1) * nn[nt][1] + z1 * h.y;
                        ((uint32_t*)d_h_bf)[((size_t)gr1 * HIDDEN + coli) >> 1] = bf2(ox, oy);
                    }
                    if (gr2 < N_NODES) {
                        uint32_t hw = dsm[lr2 * S2A + hword];
                        float2 h = __bfloat1622float2(*(__nv_bfloat162*)&hw);
                        float z0 = sigm_f(ci[nt][2] + b0), z1 = sigm_f(ci[nt][3] + b1);
                        float ox = (1.f - z0) * nn[nt][2] + z0 * h.x;
                        float oy = (1.f - z1) * nn[nt][3] + z1 * h.y;
                        ((uint32_t*)d_h_bf)[((size_t)gr2 * HIDDEN + coli) >> 1] = bf2(ox, oy);
                    }
                }
            }
        }
    }
}

// ---------------- Wcomb precompute: bf16( wih[g*128+n][:] . ggnn[l][k][:] ) ----------------
__global__ void __launch_bounds__(256) k_wcomb(const float* __restrict__ wih,
                                               const float* __restrict__ ggnn) {
    __shared__ float As[16][128];
    __shared__ float Bs[16][128];
    const float* A = wih + (size_t)blockIdx.x * 128 * HIDDEN;
    const float* B = ggnn + (size_t)blockIdx.y * HIDDEN * HIDDEN;
    __nv_bfloat16* C = d_Wcomb_bf + ((size_t)blockIdx.y * 3 + blockIdx.x) * 128 * HIDDEN;
    const int tid = threadIdx.x, tx = tid & 15, ty = tid >> 4;

    float acc[8][8];
#pragma unroll
    for (int i = 0; i < 8; i++)
#pragma unroll
        for (int j = 0; j < 8; j++) acc[i][j] = 0.f;

    for (int j0 = 0; j0 < 128; j0 += 16) {
#pragma unroll
        for (int q = tid; q < 512; q += 256) {
            int n = q >> 2, j4 = (q & 3) << 2;
            float4 va = *(const float4*)(A + (size_t)n * HIDDEN + j0 + j4);
            As[j4 + 0][n] = va.x; As[j4 + 1][n] = va.y;
            As[j4 + 2][n] = va.z; As[j4 + 3][n] = va.w;
            float4 vb = *(const float4*)(B + (size_t)n * HIDDEN + j0 + j4);
            Bs[j4 + 0][n] = vb.x; Bs[j4 + 1][n] = vb.y;
            Bs[j4 + 2][n] = vb.z; Bs[j4 + 3][n] = vb.w;
        }
        __syncthreads();
#pragma unroll
        for (int jj = 0; jj < 16; jj++) {
            float a[8], b[8];
#pragma unroll
            for (int i = 0; i < 8; i++) a[i] = As[jj][ty * 8 + i];
#pragma unroll
            for (int j = 0; j < 8; j++) b[j] = Bs[jj][tx * 8 + j];
#pragma unroll
            for (int i = 0; i < 8; i++)
#pragma unroll
                for (int j = 0; j < 8; j++) acc[i][j] = fmaf(a[i], b[j], acc[i][j]);
        }
        __syncthreads();
    }
#pragma unroll
    for (int i = 0; i < 8; i++)
#pragma unroll
        for (int j = 0; j < 8; j++)
            C[(size_t)(ty * 8 + i) * HIDDEN + tx * 8 + j] = __float2bfloat16(acc[i][j]);
}

__global__ void k_whh_bf(const float* __restrict__ whh) {
    int i = blockIdx.x * blockDim.x + threadIdx.x;  // < 49152
    d_whh_bf[i] = __float2bfloat16(whh[i]);
}

// ---------------- fc1: tf32 HMMA, A from bf16 h, 256 thr, occ 2 ----------------
__global__ void __launch_bounds__(256, 2) k_mma_fc1(
    const float* __restrict__ Bt, const float* __restrict__ bias)
{
    __shared__ uint32_t As[128 * ASTRIDE];
    __shared__ uint32_t Bs[128 * ASTRIDE];
    const int tid = threadIdx.x, lane = tid & 31, w = tid >> 5;
    const int wm = w & 3, wn = w >> 2;
    const int gid = lane >> 2, tg = lane & 3;
    const int row0 = blockIdx.x * 128;

    float c[2][8][4];
#pragma unroll
    for (int i = 0; i < 2; i++)
#pragma unroll
        for (int j = 0; j < 8; j++)
#pragma unroll
            for (int q = 0; q < 4; q++) c[i][j][q] = 0.f;

#pragma unroll
    for (int kp = 0; kp < 4; kp++) {
        if (kp) __syncthreads();
#pragma unroll
        for (int q = tid; q < 1024; q += 256) {
            int r = q >> 3, k4 = (q & 7) << 2;
            int gr = row0 + r;
            if (gr >= N_NODES) gr = N_NODES - 1;
            uint2 u = *(const uint2*)(d_h_bf + (size_t)gr * HIDDEN + kp * 32 + k4);
            float2 f0 = __bfloat1622float2(*(__nv_bfloat162*)&u.x);
            float2 f1 = __bfloat1622float2(*(__nv_bfloat162*)&u.y);
            *(uint4*)(As + r * ASTRIDE + k4) =
                make_uint4(f2tf32(f0.x), f2tf32(f0.y), f2tf32(f1.x), f2tf32(f1.y));
            float4 vb = *(const float4*)(Bt + (size_t)r * HIDDEN + kp * 32 + k4);
            *(uint4*)(Bs + r * ASTRIDE + k4) =
                make_uint4(f2tf32(vb.x), f2tf32(vb.y), f2tf32(vb.z), f2tf32(vb.w));
        }
        __syncthreads();
#pragma unroll
        for (int ks = 0; ks < 4; ks++) {
            int k0 = ks * 8;
            uint32_t af[2][4];
#pragma unroll
            for (int mt = 0; mt < 2; mt++) {
                int rb = wm * 32 + mt * 16;
                af[mt][0] = As[(rb + gid) * ASTRIDE + k0 + tg];
                af[mt][1] = As[(rb + gid + 8) * ASTRIDE + k0 + tg];
                af[mt][2] = As[(rb + gid) * ASTRIDE + k0 + tg + 4];
                af[mt][3] = As[(rb + gid + 8) * ASTRIDE + k0 + tg + 4];
            }
#pragma unroll
            for (int nt = 0; nt < 8; nt++) {
                uint32_t bf[2];
                int nb = wn * 64 + nt * 8 + gid;
                bf[0] = Bs[nb * ASTRIDE + k0 + tg];
                bf[1] = Bs[nb * ASTRIDE + k0 + tg + 4];
#pragma unroll
                for (int mt = 0; mt < 2; mt++) mma_tf32(c[mt][nt], af[mt], bf);
            }
        }
    }

#pragma unroll
    for (int mt = 0; mt < 2; mt++) {
        int r1 = row0 + wm * 32 + mt * 16 + gid;
        int r2 = r1 + 8;
#pragma unroll
        for (int nt = 0; nt < 8; nt++) {
            int coli = wn * 64 + nt * 8 + tg * 2;
            float b0 = bias[coli], b1 = bias[coli + 1];
            if (r1 < N_NODES) {
                float2 v = make_float2(c[mt][nt][0] + b0, c[mt][nt][1] + b1);
                *(float2*)(d_m + (size_t)r1 * HIDDEN + coli) = v;
            }
            if (r2 < N_NODES) {
                float2 v = make_float2(c[mt][nt][2] + b0, c[mt][nt][3] + b1);
                *(float2*)(d_m + (size_t)r2 * HIDDEN + coli) = v;
            }
        }
    }
}

// ---------------- setup kernels ----------------
__global__ void k_init() {
    int i = blockIdx.x * blockDim.x + threadIdx.x;
    if (i < N_NODES) d_deg[i] = 0;
    if (i < NUM_GRAPHS * HIDDEN) d_pool[i] = 0.f;
    if (i < NUM_GRAPHS) d_cnt[i] = 0;
    if (i < HIDDEN) { d_sum[i] = 0.f; d_sumsq[i] = 0.f; }
}

__global__ void k_copy_x(const float* __restrict__ x) {
    int i = blockIdx.x * blockDim.x + threadIdx.x;  // 3.2M float4
    float4 v = ((const float4*)x)[i];
    ((uint2*)d_h_bf)[i] = make_uint2(bf2(v.x, v.y), bf2(v.z, v.w));
}

__global__ void k_edges(const int* __restrict__ e) {
    int i = blockIdx.x * blockDim.x + threadIdx.x;
    int s = e[i];
    int d = e[N_EDGES + i];
    d_src[i] = s;
    d_dst[i] = d;
    atomicAdd(&d_deg[d], 1);
}

__global__ void k_batch_hist(const int* __restrict__ batch) {
    __shared__ int hc[NUM_GRAPHS];
    for (int i = threadIdx.x; i < NUM_GRAPHS; i += blockDim.x) hc[i] = 0;
    __syncthreads();
    int idx = blockIdx.x * blockDim.x + threadIdx.x;
    if (idx < N_NODES) atomicAdd(&hc[batch[idx]], 1);
    __syncthreads();
    for (int i = threadIdx.x; i < NUM_GRAPHS; i += blockDim.x)
        if (hc[i]) atomicAdd(&d_cnt[i], hc[i]);
}

__global__ void k_scan1() {
    __shared__ int sh[32];
    int lane = threadIdx.x & 31, warp = threadIdx.x >> 5;
    int idx = blockIdx.x * 1024 + threadIdx.x;
    int v = (idx < N_NODES) ? d_deg[idx] : 0;
#pragma unroll
    for (int o = 16; o; o >>= 1) v += __shfl_down_sync(0xFFFFFFFFu, v, o);
    if (lane == 0) sh[warp] = v;
    __syncthreads();
    if (warp == 0) {
        v = sh[lane];
#pragma unroll
        for (int o = 16; o; o >>= 1) v += __shfl_down_sync(0xFFFFFFFFu, v, o);
        if (lane == 0) d_blocksum[blockIdx.x] = v;
    }
}

__global__ void k_scan2() {
    __shared__ int s[128];
    int t = threadIdx.x;
    int v = (t < 98) ? d_blocksum[t] : 0;
    s[t] = v;
    __syncthreads();
#pragma unroll
    for (int o = 1; o < 128; o <<= 1) {
        int tmp = (t >= o) ? s[t - o] : 0;
        __syncthreads();
        s[t] += tmp;
        __syncthreads();
    }
    if (t < 98) d_blockoff[t] = s[t] - v;
    if (t == 0) d_rowptr[N_NODES] = s[97];
}

__global__ void k_scan3() {
    __shared__ int s[1024];
    int t = threadIdx.x;
    int idx = blockIdx.x * 1024 + t;
    int v = (idx < N_NODES) ? d_deg[idx] : 0;
    s[t] = v;
    __syncthreads();
#pragma unroll
    for (int o = 1; o < 1024; o <<= 1) {
        int tmp = (t >= o) ? s[t - o] : 0;
        __syncthreads();
        s[t] += tmp;
        __syncthreads();
    }
    if (idx < N_NODES) {
        int ex = d_blockoff[blockIdx.x] + s[t] - v;
        d_rowptr[idx] = ex;
        d_cursor[idx] = ex;
    }
}

__global__ void k_csr_fill() {
    int i = blockIdx.x * blockDim.x + threadIdx.x;
    int pos = atomicAdd(&d_cursor[d_dst[i]], 1);
    d_colidx[pos] = d_src[i];
}

// ---------------- CSR aggregate of h (bf16): one warp per destination node ----------------
__global__ void k_aggregate() {
    int warp = (blockIdx.x * blockDim.x + threadIdx.x) >> 5;
    int lane = threadIdx.x & 31;
    if (warp >= N_NODES) return;
    int beg = d_rowptr[warp], end = d_rowptr[warp + 1];
    const uint2* hb = (const uint2*)d_h_bf;  // 32 uint2 per row
    float4 acc = make_float4(0.f, 0.f, 0.f, 0.f);
    for (int e = beg; e < end; e++) {
        int src = d_colidx[e];
        uint2 v = hb[(size_t)src * 32 + lane];
        float2 f0 = __bfloat1622float2(*(__nv_bfloat162*)&v.x);
        float2 f1 = __bfloat1622float2(*(__nv_bfloat162*)&v.y);
        acc.x += f0.x; acc.y += f0.y; acc.z += f1.x; acc.w += f1.y;
    }
    ((uint2*)d_agg_bf)[(size_t)warp * 32 + lane] =
        make_uint2(bf2(acc.x, acc.y), bf2(acc.z, acc.w));
}

// ---------------- batchnorm + relu + mean pool + classifier ----------------
__global__ void k_bn_stats() {
    int c = threadIdx.x;
    int n0 = blockIdx.x * 500;
    int n1 = n0 + 500;
    float s = 0.f, s2 = 0.f;
    for (int n = n0; n < n1; n++) {
        float v = d_m[(size_t)n * HIDDEN + c];
        s += v;
        s2 += v * v;
    }
    atomicAdd(&d_sum[c], s);
    atomicAdd(&d_sumsq[c], s2);
}

__global__ void k_bn_final() {
    int c = threadIdx.x;
    float mu = d_sum[c] / (float)N_NODES;
    float var = d_sumsq[c] / (float)N_NODES - mu * mu;
    d_mean[c] = mu;
    d_rstd[c] = rsqrtf(var + BN_EPS);
}

__global__ void k_pool(const int* __restrict__ batch,
                       const float* __restrict__ gamma,
                       const float* __restrict__ beta) {
    int c = threadIdx.x;
    int n0 = blockIdx.x * 512;
    int n1 = n0 + 512;
    if (n1 > N_NODES) n1 = N_NODES;
    if (n0 >= N_NODES) return;
    float sc = gamma[c] * d_rstd[c];
    float mu = d_mean[c];
    float be = beta[c];
    float acc = 0.f;
    int cur = batch[n0];
    for (int n = n0; n < n1; n++) {
        int bb = batch[n];
        if (bb != cur) {
            atomicAdd(&d_pool[cur * HIDDEN + c], acc);
            acc = 0.f;
            cur = bb;
        }
        float v = (d_m[(size_t)n * HIDDEN + c] - mu) * sc + be;
        acc += fmaxf(v, 0.f);
    }
    atomicAdd(&d_pool[cur * HIDDEN + c], acc);
}

__global__ void k_final(const float* __restrict__ w2, const float* __restrict__ b2,
                        float* __restrict__ out) {
    __shared__ float sf[HIDDEN];
    __shared__ float lg[NUM_CLASSES];
    int g = blockIdx.x, t = threadIdx.x;
    float cnt = fmaxf((float)d_cnt[g], 1.f);
    sf[t] = d_pool[g * HIDDEN + t] / cnt;
    __syncthreads();
    if (t < NUM_CLASSES) {
        float s = b2[t];
        for (int k = 0; k < HIDDEN; k++) s += sf[k] * w2[t * HIDDEN + k];
        lg[t] = s;
    }
    __syncthreads();
    if (t == 0) {
        float mx = -1e30f;
        for (int c = 0; c < NUM_CLASSES; c++) mx = fmaxf(mx, lg[c]);
        float se = 0.f;
        for (int c = 0; c < NUM_CLASSES; c++) se += expf(lg[c] - mx);
        float lse = mx + logf(se);
        for (int c = 0; c < NUM_CLASSES; c++) out[g * NUM_CLASSES + c] = lg[c] - lse;
    }
}

// ---------------- launch ----------------
extern "C" void kernel_launch(void* const* d_in, const int* in_sizes, int n_in,
                              void* d_out, int out_size) {
    const float* x     = (const float*)d_in[0];
    const int*   ei    = (const int*)d_in[1];
    const int*   bat   = (const int*)d_in[2];
    const float* ggnn  = (const float*)d_in[3];
    const float* wih   = (const float*)d_in[4];
    const float* whh   = (const float*)d_in[5];
    const float* bih   = (const float*)d_in[6];
    const float* bhh   = (const float*)d_in[7];
    const float* fc1w  = (const float*)d_in[8];
    const float* fc1b  = (const float*)d_in[9];
    const float* gamma = (const float*)d_in[10];
    const float* beta  = (const float*)d_in[11];
    const float* fc2w  = (const float*)d_in[12];
    const float* fc2b  = (const float*)d_in[13];
    float* out = (float*)d_out;

    cudaFuncSetAttribute(k_gru_fused, cudaFuncAttributeMaxDynamicSharedMemorySize,
                         GRU_SMEM_BYTES);

    k_init<<<(N_NODES + 255) / 256, 256>>>();
    k_copy_x<<<(N_NODES * HIDDEN / 4) / 256, 256>>>(x);
    k_edges<<<N_EDGES / 256, 256>>>(ei);
    k_batch_hist<<<98, 1024>>>(bat);
    k_scan1<<<98, 1024>>>();
    k_scan2<<<1, 128>>>();
    k_scan3<<<98, 1024>>>();
    k_csr_fill<<<N_EDGES / 256, 256>>>();
    k_wcomb<<<dim3(3, NUM_LAYERS), 256>>>(wih, ggnn);
    k_whh_bf<<<192, 256>>>(whh);

    const int gru_blocks = (N_NODES + 63) / 64;  // 1563
    for (int l = 0; l < NUM_LAYERS; l++) {
        k_aggregate<<<(N_NODES * 32) / 256, 256>>>();
        k_gru_fused<<<gru_blocks, 512, GRU_SMEM_BYTES>>>(l, bih, bhh);
    }

    k_mma_fc1<<<(N_NODES + 127) / 128, 256>>>(fc1w, fc1b);
    k_bn_stats<<<200, 128>>>();
    k_bn_final<<<1, 128>>>();
    k_pool<<<(N_NODES + 511) / 512, 128>>>(bat, gamma, beta);
    k_final<<<NUM_GRAPHS, 128>>>(fc2w, fc2b, out);
}

// round 15
// speedup vs baseline: 1.2408x; 1.0174x over previous
#include <cuda_runtime.h>
#include <cuda_bf16.h>
#include <cstdint>

#define N_NODES 100000
#define N_EDGES 1600000
#define HIDDEN 128
#define NUM_CLASSES 10
#define NUM_LAYERS 4
#define NUM_GRAPHS 200
#define BN_EPS 1e-5f

// ---------------- scratch (static device arrays: no allocations) ----------------
__device__ __nv_bfloat16 d_h_bf[(size_t)N_NODES * HIDDEN]; // node state (bf16 only)
__device__ __nv_bfloat16 d_agg_bf[(size_t)N_NODES * HIDDEN];
__device__ float d_m[(size_t)N_NODES * HIDDEN];            // fc1 output
__device__ __nv_bfloat16 d_Wcomb_bf[NUM_LAYERS * 3 * HIDDEN * HIDDEN];
__device__ __nv_bfloat16 d_whh_bf[3 * HIDDEN * HIDDEN];
__device__ int d_src[N_EDGES];
__device__ int d_dst[N_EDGES];
__device__ int d_deg[N_NODES];
__device__ int d_rowptr[N_NODES + 1];
__device__ int d_cursor[N_NODES];
__device__ int d_colidx[N_EDGES];
__device__ int d_blocksum[128];
__device__ int d_blockoff[128];
__device__ float d_sum[HIDDEN], d_sumsq[HIDDEN], d_mean[HIDDEN], d_rstd[HIDDEN];
__device__ float d_pool[NUM_GRAPHS * HIDDEN];
__device__ int d_cnt[NUM_GRAPHS];

// ---------------- helpers ----------------
__device__ __forceinline__ float sigm_f(float x) {
    return __fdividef(1.f, 1.f + __expf(-x));
}
__device__ __forceinline__ float tanh_f(float x) {
    return 1.f - __fdividef(2.f, __expf(2.f * x) + 1.f);
}
__device__ __forceinline__ uint32_t smem_u32(const void* p) {
    uint32_t a;
    asm("{ .reg .u64 t; cvta.to.shared.u64 t, %1; cvt.u32.u64 %0, t; }" : "=r"(a) : "l"(p));
    return a;
}
__device__ __forceinline__ uint32_t f2tf32(float f) {
    uint32_t r;
    asm("cvt.rna.tf32.f32 %0, %1;" : "=r"(r) : "f"(f));
    return r;
}
__device__ __forceinline__ uint32_t bf2(float lo, float hi) {
    __nv_bfloat162 p = __floats2bfloat162_rn(lo, hi);
    return *(uint32_t*)&p;
}
__device__ __forceinline__ void mma_tf32(float* c, const uint32_t* a, const uint32_t* b) {
    asm volatile(
        "mma.sync.aligned.m16n8k8.row.col.f32.tf32.tf32.f32 "
        "{%0,%1,%2,%3}, {%4,%5,%6,%7}, {%8,%9}, {%0,%1,%2,%3};"
        : "+f"(c[0]), "+f"(c[1]), "+f"(c[2]), "+f"(c[3])
        : "r"(a[0]), "r"(a[1]), "r"(a[2]), "r"(a[3]), "r"(b[0]), "r"(b[1]));
}
__device__ __forceinline__ void mma_bf16(float* c, const uint32_t* a, const uint32_t* b) {
    asm volatile(
        "mma.sync.aligned.m16n8k16.row.col.f32.bf16.bf16.f32 "
        "{%0,%1,%2,%3}, {%4,%5,%6,%7}, {%8,%9}, {%0,%1,%2,%3};"
        : "+f"(c[0]), "+f"(c[1]), "+f"(c[2]), "+f"(c[3])
        : "r"(a[0]), "r"(a[1]), "r"(a[2]), "r"(a[3]), "r"(b[0]), "r"(b[1]));
}
__device__ __forceinline__ void cpasync16(uint32_t daddr, const void* src, int srcbytes) {
    asm volatile("cp.async.cg.shared.global [%0], [%1], 16, %2;"
                 :: "r"(daddr), "l"(src), "r"(srcbytes));
}
__device__ __forceinline__ void cpasync_commit() {
    asm volatile("cp.async.commit_group;" ::: "memory");
}

#define ASTRIDE 36
// gru smem (uint32 words, each = one bf16x2): A [64 rows][132], B 4 x [128][36]
#define S2A 132
#define S2B 36
#define AS_W (64 * S2A)
#define BS_W (128 * S2B)
#define NBUF 4
#define GRU_SMEM_BYTES ((AS_W + NBUF * BS_W) * 4)  // 107520 B -> 2 CTAs/SM

// ============ fused GRU layer (bf16 MMA): 64 rows/block, 512 thr, 4-deep cp.async ============
// Gate g: out = hsum @ Wcomb_g^T + h @ Whh_g^T (K=256 = 4 sub-chunks of 64 halves).
// 12 chunks: pass R(g=0) 0-3, N(g=2) 4-7, Z(g=1) 8-11.
// h state is bf16-only; old h for the Z blend is read back from the smem A tile.
// rr doubles as the n-gate store after pass N (in-place overwrite).
__device__ __forceinline__ void gru_issueB(uint32_t bufaddr, const __nv_bfloat16* __restrict__ wcomb,
                                           int chunk, int tid) {
    int pass = chunk >> 2;
    int g = (pass == 0) ? 0 : (pass == 1) ? 2 : 1;
    int sub = chunk & 3;
    const __nv_bfloat16* base = ((sub < 2) ? wcomb : d_whh_bf) +
                                (size_t)g * 128 * HIDDEN + (sub & 1) * 64;
#pragma unroll
    for (int q = tid; q < 1024; q += 512) {
        int n = q >> 3, o = q & 7;
        cpasync16(bufaddr + (n * S2B + o * 4) * 4, base + (size_t)n * HIDDEN + o * 8, 16);
    }
    cpasync_commit();
}

__global__ void __launch_bounds__(512, 2) k_gru_fused(
    int layer, const float* __restrict__ bih, const float* __restrict__ bhh)
{
    extern __shared__ uint32_t dsm[];
    const __nv_bfloat16* wcomb = d_Wcomb_bf + (size_t)layer * 3 * HIDDEN * HIDDEN;
    const uint32_t sb = smem_u32(dsm);
    const uint32_t sbB = sb + AS_W * 4;

    const int tid = threadIdx.x, lane = tid & 31, w = tid >> 5;
    const int wm = w & 3, wn = w >> 2;  // 4 m-strips x 4 n-strips
    const int gid = lane >> 2, tg = lane & 3;
    const int row0 = blockIdx.x * 64;
    const int lr1 = wm * 16 + gid, lr2 = lr1 + 8;

    // ---- prologue: async-stage A tile ([agg_bf | h_bf], 64x256 halves) + chunks 0,1,2 ----
#pragma unroll
    for (int q = tid; q < 2048; q += 512) {
        int r = q >> 5, o = q & 31;  // 32 x 16B per row (16 agg + 16 h)
        int gr = row0 + r;
        int ok = (gr < N_NODES);
        if (!ok) gr = 0;
        const __nv_bfloat16* src = (o < 16) ? d_agg_bf + (size_t)gr * HIDDEN + o * 8
                                            : d_h_bf + (size_t)gr * HIDDEN + (o - 16) * 8;
        cpasync16(sb + (r * S2A + o * 4) * 4, src, ok ? 16 : 0);
    }
    gru_issueB(sbB, wcomb, 0, tid);                     // A + B0 in one group
    gru_issueB(sbB + BS_W * 4, wcomb, 1, tid);          // B1
    gru_issueB(sbB + 2 * BS_W * 4, wcomb, 2, tid);      // B2

    float rr[4][4], ci[4][4], ch[4][4];  // rr also holds n after pass N
#pragma unroll
    for (int j = 0; j < 4; j++)
#pragma unroll
        for (int q = 0; q < 4; q++) { ci[j][q] = 0.f; ch[j][q] = 0.f; }

    for (int it = 0; it < 12; it++) {
        if (it < 10) asm volatile("cp.async.wait_group 2;" ::: "memory");
        else if (it == 10) asm volatile("cp.async.wait_group 1;" ::: "memory");
        else asm volatile("cp.async.wait_group 0;" ::: "memory");
        __syncthreads();

        if (it + 3 < 12) gru_issueB(sbB + ((it + 3) & 3) * BS_W * 4, wcomb, it + 3, tid);

        const uint32_t* BS = dsm + AS_W + (it & 3) * BS_W;
        const int pass = it >> 2, sub = it & 3;
        float(*acc)[4] = (pass == 1 && sub >= 2) ? ch : ci;
        const int kbase = sub * 32;  // half2 units
#pragma unroll
        for (int ks = 0; ks < 4; ks++) {
            int kb = kbase + ks * 8;
            uint32_t af[4];
            af[0] = dsm[lr1 * S2A + kb + tg];
            af[1] = dsm[lr2 * S2A + kb + tg];
            af[2] = dsm[lr1 * S2A + kb + tg + 4];
            af[3] = dsm[lr2 * S2A + kb + tg + 4];
#pragma unroll
            for (int nt = 0; nt < 4; nt++) {
                uint32_t bf[2];
                int nb = wn * 32 + nt * 8 + gid;
                bf[0] = BS[nb * S2B + ks * 8 + tg];
                bf[1] = BS[nb * S2B + ks * 8 + tg + 4];
                mma_bf16(acc[nt], af, bf);
            }
        }

        if (sub == 3) {
            if (pass == 0) {  // R: rr = sigmoid
#pragma unroll
                for (int nt = 0; nt < 4; nt++) {
                    int coli = wn * 32 + nt * 8 + tg * 2;
                    float b0 = bih[coli] + bhh[coli];
                    float b1 = bih[coli + 1] + bhh[coli + 1];
                    rr[nt][0] = sigm_f(ci[nt][0] + b0);
                    rr[nt][1] = sigm_f(ci[nt][1] + b1);
                    rr[nt][2] = sigm_f(ci[nt][2] + b0);
                    rr[nt][3] = sigm_f(ci[nt][3] + b1);
#pragma unroll
                    for (int q = 0; q < 4; q++) ci[nt][q] = 0.f;
                }
            } else if (pass == 1) {  // N: rr <- tanh(i_n + r*(h_n)) (in-place)
#pragma unroll
                for (int nt = 0; nt < 4; nt++) {
                    int coli = wn * 32 + nt * 8 + tg * 2;
                    float bi0 = bih[256 + coli], bi1 = bih[256 + coli + 1];
                    float bh0 = bhh[256 + coli], bh1 = bhh[256 + coli + 1];
                    rr[nt][0] = tanh_f(ci[nt][0] + bi0 + rr[nt][0] * (ch[nt][0] + bh0));
                    rr[nt][1] = tanh_f(ci[nt][1] + bi1 + rr[nt][1] * (ch[nt][1] + bh1));
                    rr[nt][2] = tanh_f(ci[nt][2] + bi0 + rr[nt][2] * (ch[nt][2] + bh0));
                    rr[nt][3] = tanh_f(ci[nt][3] + bi1 + rr[nt][3] * (ch[nt][3] + bh1));
#pragma unroll
                    for (int q = 0; q < 4; q++) ci[nt][q] = 0.f;
                }
            } else {  // Z: h_new = (1-z)*n + z*h_old; h_old from smem A tile, n in rr
                int gr1 = row0 + lr1, gr2 = row0 + lr2;
#pragma unroll
                for (int nt = 0; nt < 4; nt++) {
                    int coli = wn * 32 + nt * 8 + tg * 2;
                    int hword = 64 + (coli >> 1);  // h half of A row, bf16x2 word
                    float b0 = bih[128 + coli] + bhh[128 + coli];
                    float b1 = bih[128 + coli + 1] + bhh[128 + coli + 1];
                    if (gr1 < N_NODES) {
                        uint32_t hw = dsm[lr1 * S2A + hword];
                        float2 h = __bfloat1622float2(*(__nv_bfloat162*)&hw);
                        float z0 = sigm_f(ci[nt][0] + b0), z1 = sigm_f(ci[nt][1] + b1);
                        float ox = (1.f - z0) * rr[nt][0] + z0 * h.x;
                        float oy = (1.f - z1) * rr[nt][1] + z1 * h.y;
                        ((uint32_t*)d_h_bf)[((size_t)gr1 * HIDDEN + coli) >> 1] = bf2(ox, oy);
                    }
                    if (gr2 < N_NODES) {
                        uint32_t hw = dsm[lr2 * S2A + hword];
                        float2 h = __bfloat1622float2(*(__nv_bfloat162*)&hw);
                        float z0 = sigm_f(ci[nt][2] + b0), z1 = sigm_f(ci[nt][3] + b1);
                        float ox = (1.f - z0) * rr[nt][2] + z0 * h.x;
                        float oy = (1.f - z1) * rr[nt][3] + z1 * h.y;
                        ((uint32_t*)d_h_bf)[((size_t)gr2 * HIDDEN + coli) >> 1] = bf2(ox, oy);
                    }
                }
            }
        }
    }
}

// ---------------- Wcomb precompute: bf16( wih[g*128+n][:] . ggnn[l][k][:] ) ----------------
__global__ void __launch_bounds__(256) k_wcomb(const float* __restrict__ wih,
                                               const float* __restrict__ ggnn) {
    __shared__ float As[16][128];
    __shared__ float Bs[16][128];
    const float* A = wih + (size_t)blockIdx.x * 128 * HIDDEN;
    const float* B = ggnn + (size_t)blockIdx.y * HIDDEN * HIDDEN;
    __nv_bfloat16* C = d_Wcomb_bf + ((size_t)blockIdx.y * 3 + blockIdx.x) * 128 * HIDDEN;
    const int tid = threadIdx.x, tx = tid & 15, ty = tid >> 4;

    float acc[8][8];
#pragma unroll
    for (int i = 0; i < 8; i++)
#pragma unroll
        for (int j = 0; j < 8; j++) acc[i][j] = 0.f;

    for (int j0 = 0; j0 < 128; j0 += 16) {
#pragma unroll
        for (int q = tid; q < 512; q += 256) {
            int n = q >> 2, j4 = (q & 3) << 2;
            float4 va = *(const float4*)(A + (size_t)n * HIDDEN + j0 + j4);
            As[j4 + 0][n] = va.x; As[j4 + 1][n] = va.y;
            As[j4 + 2][n] = va.z; As[j4 + 3][n] = va.w;
            float4 vb = *(const float4*)(B + (size_t)n * HIDDEN + j0 + j4);
            Bs[j4 + 0][n] = vb.x; Bs[j4 + 1][n] = vb.y;
            Bs[j4 + 2][n] = vb.z; Bs[j4 + 3][n] = vb.w;
        }
        __syncthreads();
#pragma unroll
        for (int jj = 0; jj < 16; jj++) {
            float a[8], b[8];
#pragma unroll
            for (int i = 0; i < 8; i++) a[i] = As[jj][ty * 8 + i];
#pragma unroll
            for (int j = 0; j < 8; j++) b[j] = Bs[jj][tx * 8 + j];
#pragma unroll
            for (int i = 0; i < 8; i++)
#pragma unroll
                for (int j = 0; j < 8; j++) acc[i][j] = fmaf(a[i], b[j], acc[i][j]);
        }
        __syncthreads();
    }
#pragma unroll
    for (int i = 0; i < 8; i++)
#pragma unroll
        for (int j = 0; j < 8; j++)
            C[(size_t)(ty * 8 + i) * HIDDEN + tx * 8 + j] = __float2bfloat16(acc[i][j]);
}

__global__ void k_whh_bf(const float* __restrict__ whh) {
    int i = blockIdx.x * blockDim.x + threadIdx.x;  // < 49152
    d_whh_bf[i] = __float2bfloat16(whh[i]);
}

// ---------------- fc1: tf32 HMMA, A from bf16 h, 256 thr, occ 2 ----------------
__global__ void __launch_bounds__(256, 2) k_mma_fc1(
    const float* __restrict__ Bt, const float* __restrict__ bias)
{
    __shared__ uint32_t As[128 * ASTRIDE];
    __shared__ uint32_t Bs[128 * ASTRIDE];
    const int tid = threadIdx.x, lane = tid & 31, w = tid >> 5;
    const int wm = w & 3, wn = w >> 2;
    const int gid = lane >> 2, tg = lane & 3;
    const int row0 = blockIdx.x * 128;

    float c[2][8][4];
#pragma unroll
    for (int i = 0; i < 2; i++)
#pragma unroll
        for (int j = 0; j < 8; j++)
#pragma unroll
            for (int q = 0; q < 4; q++) c[i][j][q] = 0.f;

#pragma unroll
    for (int kp = 0; kp < 4; kp++) {
        if (kp) __syncthreads();
#pragma unroll
        for (int q = tid; q < 1024; q += 256) {
            int r = q >> 3, k4 = (q & 7) << 2;
            int gr = row0 + r;
            if (gr >= N_NODES) gr = N_NODES - 1;
            uint2 u = *(const uint2*)(d_h_bf + (size_t)gr * HIDDEN + kp * 32 + k4);
            float2 f0 = __bfloat1622float2(*(__nv_bfloat162*)&u.x);
            float2 f1 = __bfloat1622float2(*(__nv_bfloat162*)&u.y);
            *(uint4*)(As + r * ASTRIDE + k4) =
                make_uint4(f2tf32(f0.x), f2tf32(f0.y), f2tf32(f1.x), f2tf32(f1.y));
            float4 vb = *(const float4*)(Bt + (size_t)r * HIDDEN + kp * 32 + k4);
            *(uint4*)(Bs + r * ASTRIDE + k4) =
                make_uint4(f2tf32(vb.x), f2tf32(vb.y), f2tf32(vb.z), f2tf32(vb.w));
        }
        __syncthreads();
#pragma unroll
        for (int ks = 0; ks < 4; ks++) {
            int k0 = ks * 8;
            uint32_t af[2][4];
#pragma unroll
            for (int mt = 0; mt < 2; mt++) {
                int rb = wm * 32 + mt * 16;
                af[mt][0] = As[(rb + gid) * ASTRIDE + k0 + tg];
                af[mt][1] = As[(rb + gid + 8) * ASTRIDE + k0 + tg];
                af[mt][2] = As[(rb + gid) * ASTRIDE + k0 + tg + 4];
                af[mt][3] = As[(rb + gid + 8) * ASTRIDE + k0 + tg + 4];
            }
#pragma unroll
            for (int nt = 0; nt < 8; nt++) {
                uint32_t bf[2];
                int nb = wn * 64 + nt * 8 + gid;
                bf[0] = Bs[nb * ASTRIDE + k0 + tg];
                bf[1] = Bs[nb * ASTRIDE + k0 + tg + 4];
#pragma unroll
                for (int mt = 0; mt < 2; mt++) mma_tf32(c[mt][nt], af[mt], bf);
            }
        }
    }

#pragma unroll
    for (int mt = 0; mt < 2; mt++) {
        int r1 = row0 + wm * 32 + mt * 16 + gid;
        int r2 = r1 + 8;
#pragma unroll
        for (int nt = 0; nt < 8; nt++) {
            int coli = wn * 64 + nt * 8 + tg * 2;
            float b0 = bias[coli], b1 = bias[coli + 1];
            if (r1 < N_NODES) {
                float2 v = make_float2(c[mt][nt][0] + b0, c[mt][nt][1] + b1);
                *(float2*)(d_m + (size_t)r1 * HIDDEN + coli) = v;
            }
            if (r2 < N_NODES) {
                float2 v = make_float2(c[mt][nt][2] + b0, c[mt][nt][3] + b1);
                *(float2*)(d_m + (size_t)r2 * HIDDEN + coli) = v;
            }
        }
    }
}

// ---------------- setup kernels ----------------
__global__ void k_init() {
    int i = blockIdx.x * blockDim.x + threadIdx.x;
    if (i < N_NODES) d_deg[i] = 0;
    if (i < NUM_GRAPHS * HIDDEN) d_pool[i] = 0.f;
    if (i < NUM_GRAPHS) d_cnt[i] = 0;
    if (i < HIDDEN) { d_sum[i] = 0.f; d_sumsq[i] = 0.f; }
}

__global__ void k_copy_x(const float* __restrict__ x) {
    int i = blockIdx.x * blockDim.x + threadIdx.x;  // 3.2M float4
    float4 v = ((const float4*)x)[i];
    ((uint2*)d_h_bf)[i] = make_uint2(bf2(v.x, v.y), bf2(v.z, v.w));
}

__global__ void k_edges(const int* __restrict__ e) {
    int i = blockIdx.x * blockDim.x + threadIdx.x;
    int s = e[i];
    int d = e[N_EDGES + i];
    d_src[i] = s;
    d_dst[i] = d;
    atomicAdd(&d_deg[d], 1);
}

__global__ void k_batch_hist(const int* __restrict__ batch) {
    __shared__ int hc[NUM_GRAPHS];
    for (int i = threadIdx.x; i < NUM_GRAPHS; i += blockDim.x) hc[i] = 0;
    __syncthreads();
    int idx = blockIdx.x * blockDim.x + threadIdx.x;
    if (idx < N_NODES) atomicAdd(&hc[batch[idx]], 1);
    __syncthreads();
    for (int i = threadIdx.x; i < NUM_GRAPHS; i += blockDim.x)
        if (hc[i]) atomicAdd(&d_cnt[i], hc[i]);
}

__global__ void k_scan1() {
    __shared__ int sh[32];
    int lane = threadIdx.x & 31, warp = threadIdx.x >> 5;
    int idx = blockIdx.x * 1024 + threadIdx.x;
    int v = (idx < N_NODES) ? d_deg[idx] : 0;
#pragma unroll
    for (int o = 16; o; o >>= 1) v += __shfl_down_sync(0xFFFFFFFFu, v, o);
    if (lane == 0) sh[warp] = v;
    __syncthreads();
    if (warp == 0) {
        v = sh[lane];
#pragma unroll
        for (int o = 16; o; o >>= 1) v += __shfl_down_sync(0xFFFFFFFFu, v, o);
        if (lane == 0) d_blocksum[blockIdx.x] = v;
    }
}

__global__ void k_scan2() {
    __shared__ int s[128];
    int t = threadIdx.x;
    int v = (t < 98) ? d_blocksum[t] : 0;
    s[t] = v;
    __syncthreads();
#pragma unroll
    for (int o = 1; o < 128; o <<= 1) {
        int tmp = (t >= o) ? s[t - o] : 0;
        __syncthreads();
        s[t] += tmp;
        __syncthreads();
    }
    if (t < 98) d_blockoff[t] = s[t] - v;
    if (t == 0) d_rowptr[N_NODES] = s[97];
}

__global__ void k_scan3() {
    __shared__ int s[1024];
    int t = threadIdx.x;
    int idx = blockIdx.x * 1024 + t;
    int v = (idx < N_NODES) ? d_deg[idx] : 0;
    s[t] = v;
    __syncthreads();
#pragma unroll
    for (int o = 1; o < 1024; o <<= 1) {
        int tmp = (t >= o) ? s[t - o] : 0;
        __syncthreads();
        s[t] += tmp;
        __syncthreads();
    }
    if (idx < N_NODES) {
        int ex = d_blockoff[blockIdx.x] + s[t] - v;
        d_rowptr[idx] = ex;
        d_cursor[idx] = ex;
    }
}

__global__ void k_csr_fill() {
    int i = blockIdx.x * blockDim.x + threadIdx.x;
    int pos = atomicAdd(&d_cursor[d_dst[i]], 1);
    d_colidx[pos] = d_src[i];
}

// ---------------- CSR aggregate of h (bf16): one warp per destination node ----------------
__global__ void k_aggregate() {
    int warp = (blockIdx.x * blockDim.x + threadIdx.x) >> 5;
    int lane = threadIdx.x & 31;
    if (warp >= N_NODES) return;
    int beg = d_rowptr[warp], end = d_rowptr[warp + 1];
    const uint2* hb = (const uint2*)d_h_bf;  // 32 uint2 per row
    float4 acc = make_float4(0.f, 0.f, 0.f, 0.f);
    for (int e = beg; e < end; e++) {
        int src = d_colidx[e];
        uint2 v = hb[(size_t)src * 32 + lane];
        float2 f0 = __bfloat1622float2(*(__nv_bfloat162*)&v.x);
        float2 f1 = __bfloat1622float2(*(__nv_bfloat162*)&v.y);
        acc.x += f0.x; acc.y += f0.y; acc.z += f1.x; acc.w += f1.y;
    }
    ((uint2*)d_agg_bf)[(size_t)warp * 32 + lane] =
        make_uint2(bf2(acc.x, acc.y), bf2(acc.z, acc.w));
}

// ---------------- batchnorm + relu + mean pool + classifier ----------------
__global__ void k_bn_stats() {
    int c = threadIdx.x;
    int n0 = blockIdx.x * 500;
    int n1 = n0 + 500;
    float s = 0.f, s2 = 0.f;
    for (int n = n0; n < n1; n++) {
        float v = d_m[(size_t)n * HIDDEN + c];
        s += v;
        s2 += v * v;
    }
    atomicAdd(&d_sum[c], s);
    atomicAdd(&d_sumsq[c], s2);
}

__global__ void k_bn_final() {
    int c = threadIdx.x;
    float mu = d_sum[c] / (float)N_NODES;
    float var = d_sumsq[c] / (float)N_NODES - mu * mu;
    d_mean[c] = mu;
    d_rstd[c] = rsqrtf(var + BN_EPS);
}

__global__ void k_pool(const int* __restrict__ batch,
                       const float* __restrict__ gamma,
                       const float* __restrict__ beta) {
    int c = threadIdx.x;
    int n0 = blockIdx.x * 512;
    int n1 = n0 + 512;
    if (n1 > N_NODES) n1 = N_NODES;
    if (n0 >= N_NODES) return;
    float sc = gamma[c] * d_rstd[c];
    float mu = d_mean[c];
    float be = beta[c];
    float acc = 0.f;
    int cur = batch[n0];
    for (int n = n0; n < n1; n++) {
        int bb = batch[n];
        if (bb != cur) {
            atomicAdd(&d_pool[cur * HIDDEN + c], acc);
            acc = 0.f;
            cur = bb;
        }
        float v = (d_m[(size_t)n * HIDDEN + c] - mu) * sc + be;
        acc += fmaxf(v, 0.f);
    }
    atomicAdd(&d_pool[cur * HIDDEN + c], acc);
}

__global__ void k_final(const float* __restrict__ w2, const float* __restrict__ b2,
                        float* __restrict__ out) {
    __shared__ float sf[HIDDEN];
    __shared__ float lg[NUM_CLASSES];
    int g = blockIdx.x, t = threadIdx.x;
    float cnt = fmaxf((float)d_cnt[g], 1.f);
    sf[t] = d_pool[g * HIDDEN + t] / cnt;
    __syncthreads();
    if (t < NUM_CLASSES) {
        float s = b2[t];
        for (int k = 0; k < HIDDEN; k++) s += sf[k] * w2[t * HIDDEN + k];
        lg[t] = s;
    }
    __syncthreads();
    if (t == 0) {
        float mx = -1e30f;
        for (int c = 0; c < NUM_CLASSES; c++) mx = fmaxf(mx, lg[c]);
        float se = 0.f;
        for (int c = 0; c < NUM_CLASSES; c++) se += expf(lg[c] - mx);
        float lse = mx + logf(se);
        for (int c = 0; c < NUM_CLASSES; c++) out[g * NUM_CLASSES + c] = lg[c] - lse;
    }
}

// ---------------- launch ----------------
extern "C" void kernel_launch(void* const* d_in, const int* in_sizes, int n_in,
                              void* d_out, int out_size) {
    const float* x     = (const float*)d_in[0];
    const int*   ei    = (const int*)d_in[1];
    const int*   bat   = (const int*)d_in[2];
    const float* ggnn  = (const float*)d_in[3];
    const float* wih   = (const float*)d_in[4];
    const float* whh   = (const float*)d_in[5];
    const float* bih   = (const float*)d_in[6];
    const float* bhh   = (const float*)d_in[7];
    const float* fc1w  = (const float*)d_in[8];
    const float* fc1b  = (const float*)d_in[9];
    const float* gamma = (const float*)d_in[10];
    const float* beta  = (const float*)d_in[11];
    const float* fc2w  = (const float*)d_in[12];
    const float* fc2b  = (const float*)d_in[13];
    float* out = (float*)d_out;

    cudaFuncSetAttribute(k_gru_fused, cudaFuncAttributeMaxDynamicSharedMemorySize,
                         GRU_SMEM_BYTES);

    k_init<<<(N_NODES + 255) / 256, 256>>>();
    k_copy_x<<<(N_NODES * HIDDEN / 4) / 256, 256>>>(x);
    k_edges<<<N_EDGES / 256, 256>>>(ei);
    k_batch_hist<<<98, 1024>>>(bat);
    k_scan1<<<98, 1024>>>();
    k_scan2<<<1, 128>>>();
    k_scan3<<<98, 1024>>>();
    k_csr_fill<<<N_EDGES / 256, 256>>>();
    k_wcomb<<<dim3(3, NUM_LAYERS), 256>>>(wih, ggnn);
    k_whh_bf<<<192, 256>>>(whh);

    const int gru_blocks = (N_NODES + 63) / 64;  // 1563
    for (int l = 0; l < NUM_LAYERS; l++) {
        k_aggregate<<<(N_NODES * 32) / 256, 256>>>();
        k_gru_fused<<<gru_blocks, 512, GRU_SMEM_BYTES>>>(l, bih, bhh);
    }

    k_mma_fc1<<<(N_NODES + 127) / 128, 256>>>(fc1w, fc1b);
    k_bn_stats<<<200, 128>>>();
    k_bn_final<<<1, 128>>>();
    k_pool<<<(N_NODES + 511) / 512, 128>>>(bat, gamma, beta);
    k_final<<<NUM_GRAPHS, 128>>>(fc2w, fc2b, out);
}